// round 11
// baseline (speedup 1.0000x reference)
#include <cuda_runtime.h>
#include <cuda_fp16.h>

#define B_ 8
#define C_ 2
#define F_ 256
#define T_ 2048
#define EPSV 1e-10f

// gaussian 1D (sigma=1, ws=5) separable factor, symmetric [W0,W1,W2,W1,W0]
#define W0 0.054488684548904895f
#define W1 0.24420134200323332f
#define W2 0.4026199468917436f

// ---- smem byte layout (channel-packed, 4 CTA/SM) ----
// HT scratch: 3 transposed planes [col 0..31][row 0..35] half2, col pitch 36 half2
//   HT_B(p) = p*4608 -> [0, 13824)
// SX float2 40x41 = 13120 overlays [0,13120) (dead after stage 1)
// UU @13824: 38x39 x uint2{half2 ux, half2 uy} = 11856 -> [13824, 25680)
// F planes @25680: 6 planes half2 36x36 pitch 36 (P0,P1,P2,P6,P7,P8), 5184 each -> 56784
//   (planes contiguous: a 3-plane group = 108 consecutive 144B rows -> flattened hpass)
// FB (curvature) overlays FP(0) after entropy group consumed it.
#define HT_B(p) ((p) * 4608)
#define UU_B    13824
#define FP_B(q) (25680 + (q) * 5184)
#define FB_B    FP_B(0)
#define SMEM_BYTES 56784

#define W0H __float2half2_rn(W0)
#define W1H __float2half2_rn(W1)
#define W2H __float2half2_rn(W2)

// ---- f32x2 packed helpers (sm_103a) ----
__device__ __forceinline__ float2 f2add(float2 a, float2 b) {
    unsigned long long ua = *(unsigned long long*)&a, ub = *(unsigned long long*)&b, ur;
    asm("add.rn.f32x2 %0, %1, %2;" : "=l"(ur) : "l"(ua), "l"(ub));
    return *(float2*)&ur;
}
__device__ __forceinline__ float2 f2mul(float2 a, float2 b) {
    unsigned long long ua = *(unsigned long long*)&a, ub = *(unsigned long long*)&b, ur;
    asm("mul.rn.f32x2 %0, %1, %2;" : "=l"(ur) : "l"(ua), "l"(ub));
    return *(float2*)&ur;
}
__device__ __forceinline__ float2 f2fma(float2 a, float2 b, float2 c) {
    unsigned long long ua = *(unsigned long long*)&a, ub = *(unsigned long long*)&b,
                       uc = *(unsigned long long*)&c, ur;
    asm("fma.rn.f32x2 %0, %1, %2, %3;" : "=l"(ur) : "l"(ua), "l"(ub), "l"(uc));
    return *(float2*)&ur;
}
__device__ __forceinline__ float2 f2sub(float2 a, float2 b) {
    return f2fma(b, make_float2(-1.f, -1.f), a);
}
__device__ __forceinline__ __half2 g5h(__half2 a, __half2 b, __half2 c, __half2 d, __half2 e) {
    return __hfma2(W0H, __hadd2(a, e), __hfma2(W1H, __hadd2(b, d), __hmul2(W2H, c)));
}
__device__ __forceinline__ float2 h2f(unsigned u) {
    __half2 h = *(__half2*)&u;
    return __half22float2(h);
}
__device__ __forceinline__ unsigned f2h(float2 v) {
    __half2 h = __floats2half2_rn(v.x, v.y);
    return *(unsigned*)&h;
}
#define H2C(u) (*(__half2*)&(u))

// FLATTENED horizontal 5-tap over THREE contiguous F planes -> HT0..HT2.
// 108 source rows (stride 144B) over 4 warp-iterations (84% lane efficiency
// vs 56% for per-plane dispatch).
__device__ __forceinline__ void hpass3(char* smb, int fsrc_b, int tx, int ty) {
    int c0 = 4 * ty;
#pragma unroll
    for (int it = 0; it < 4; it++) {
        int idx = it * 32 + tx;          // 0..127; rows 0..107 valid
        if (idx < 108) {
            const char* fb = smb + fsrc_b + idx * 144 + c0 * 4;
            uint4 qa = *(const uint4*)fb;
            uint4 qb = *(const uint4*)(fb + 16);
            __half2 h0 = H2C(qa.x), h1 = H2C(qa.y), h2 = H2C(qa.z), h3 = H2C(qa.w);
            __half2 h4 = H2C(qb.x), h5 = H2C(qb.y), h6 = H2C(qb.z), h7 = H2C(qb.w);
            __half2 o0 = g5h(h0, h1, h2, h3, h4);
            __half2 o1 = g5h(h1, h2, h3, h4, h5);
            __half2 o2 = g5h(h2, h3, h4, h5, h6);
            __half2 o3 = g5h(h3, h4, h5, h6, h7);
            int p = (idx >= 72) ? 2 : ((idx >= 36) ? 1 : 0);
            int r = idx - p * 36;
            char* hb = smb + HT_B(0) + p * 4608 + (c0 * 36 + r) * 4;
            *(unsigned*)(hb)       = *(unsigned*)&o0;
            *(unsigned*)(hb + 144) = *(unsigned*)&o1;
            *(unsigned*)(hb + 288) = *(unsigned*)&o2;
            *(unsigned*)(hb + 432) = *(unsigned*)&o3;
        }
    }
}

// single-plane horizontal pass (group-3 FB only)
__device__ __forceinline__ void hpass_f(char* smb, int fsrc_b, int htp_b, int tx, int ty) {
    int c0 = 4 * ty;
#pragma unroll
    for (int it = 0; it < 2; it++) {
        int r = (it == 0) ? tx : 32 + tx;
        if (it == 1 && tx >= 4) break;
        const char* fb = smb + fsrc_b + (r * 36 + c0) * 4;
        uint4 qa = *(const uint4*)fb;
        uint4 qb = *(const uint4*)(fb + 16);
        __half2 h0 = H2C(qa.x), h1 = H2C(qa.y), h2 = H2C(qa.z), h3 = H2C(qa.w);
        __half2 h4 = H2C(qb.x), h5 = H2C(qb.y), h6 = H2C(qb.z), h7 = H2C(qb.w);
        __half2 o0 = g5h(h0, h1, h2, h3, h4);
        __half2 o1 = g5h(h1, h2, h3, h4, h5);
        __half2 o2 = g5h(h2, h3, h4, h5, h6);
        __half2 o3 = g5h(h3, h4, h5, h6, h7);
        char* hb = smb + htp_b + (c0 * 36 + r) * 4;
        *(unsigned*)(hb)       = *(unsigned*)&o0;
        *(unsigned*)(hb + 144) = *(unsigned*)&o1;
        *(unsigned*)(hb + 288) = *(unsigned*)&o2;
        *(unsigned*)(hb + 432) = *(unsigned*)&o3;
    }
}

// ---- stage 1 specialized on border checking (CHK=false for interior CTAs) ----
template<bool CHK>
__device__ __forceinline__ void stage1_run(char* smb, const float2* SX,
                                           int tid, int t0, int f0)
{
    const float2 two = make_float2(2.f, 2.f);
    const float2 e8  = make_float2(0.125f, 0.125f);
    const float2 ep2 = make_float2(EPSV, EPSV);
    int cc = tid % 38;
    int q  = tid / 38;
    if (q < 6) {
        int r  = 7 * q;
        int rN = min(r + 7, 38);
        const float2* p = SX + r * 41 + cc;
        float2 a0 = p[0], a1 = p[1], a2 = p[2];
        p += 41;
        float2 b0 = p[0], b1 = p[1], b2 = p[2];
        bool inc = !CHK || (unsigned)(t0 - 3 + cc) < T_;
        for (; r < rN; r++) {
            const float2* pc = SX + (r + 2) * 41 + cc;
            float2 c0v = pc[0], c1v = pc[1], c2v = pc[2];
            float2 gtv = f2mul(e8, f2fma(two, f2sub(b2, b0),
                              f2add(f2sub(a2, a0), f2sub(c2v, c0v))));
            float2 gfv = f2mul(e8, f2fma(two, f2sub(c1v, a1),
                              f2add(f2sub(c0v, a0), f2sub(c2v, a2))));
            bool in = !CHK || (inc && ((unsigned)(f0 - 3 + r) < F_));
            float2 ux2 = make_float2(0.f, 0.f), uy2 = ux2;
            float2 txe = ux2;
            if (in) {
                txe = f2add(gtv, ep2);
                float2 r2v = f2fma(gfv, gfv, f2mul(txe, txe));
                float2 rin;
                rin.x = rsqrtf(fmaxf(r2v.x, 1e-30f));
                rin.y = rsqrtf(fmaxf(r2v.y, 1e-30f));
                ux2 = f2mul(txe, rin);
                uy2 = f2mul(gfv, rin);
            } else {
                gfv = make_float2(0.f, 0.f);
                gtv = gfv;
            }
            *(uint2*)(smb + UU_B + (r * 39 + cc) * 8) =
                make_uint2(f2h(ux2), f2h(uy2));
            if (r >= 1 && r <= 36 && cc >= 1 && cc <= 36) {
                int o = (r - 1) * 36 + (cc - 1);
                // mag2/r2 = 1 + O(eps/mag2): tensor fields collapse to raw products
                float2 P0 = f2mul(txe, txe);
                float2 P1 = f2mul(gfv, gfv);
                float2 P2 = f2mul(txe, gfv);
                float2 P6 = f2mul(b1, b1);       // b1 zero-filled at borders
                float2 P7, P8;
                if (in) {
                    P7.x = __fdividef(1.f, 1.f + fabsf(gtv.x));
                    P7.y = __fdividef(1.f, 1.f + fabsf(gtv.y));
                } else {
                    P7 = make_float2(0.f, 0.f);
                }
                P8.x = fabsf(gfv.x);
                P8.y = fabsf(gfv.y);
                *(unsigned*)(smb + FP_B(0) + o * 4) = f2h(P0);
                *(unsigned*)(smb + FP_B(1) + o * 4) = f2h(P1);
                *(unsigned*)(smb + FP_B(2) + o * 4) = f2h(P2);
                *(unsigned*)(smb + FP_B(3) + o * 4) = f2h(P6);
                *(unsigned*)(smb + FP_B(4) + o * 4) = f2h(P7);
                *(unsigned*)(smb + FP_B(5) + o * 4) = f2h(P8);
            }
            a0 = b0; a1 = b1; a2 = b2;
            b0 = c0v; b1 = c1v; b2 = c2v;
        }
    }
}

__global__ void __launch_bounds__(256, 4)
asa_kernel(const float* __restrict__ spec, float* __restrict__ out)
{
    extern __shared__ float sm[];
    char*   smb = (char*)sm;
    float2* SX  = (float2*)smb;   // 40 x 41 channel pair (overlaid by HT later)

    const int tx  = threadIdx.x;   // 0..31
    const int ty  = threadIdx.y;   // 0..7
    const int tid = ty * 32 + tx;
    const int t0  = blockIdx.x * 32;
    const int f0  = blockIdx.y * 32;
    const int b   = blockIdx.z;

    const size_t FT   = (size_t)F_ * T_;
    const size_t MSTR = (size_t)B_ * FT;
    const float* img0 = spec + (size_t)(b * 2) * FT;
    const float* img1 = img0 + FT;
    float* obase = out + (size_t)b * FT + (size_t)(f0 + 4 * ty) * T_ + t0 + tx;

    const bool interior = (f0 >= 4) && (f0 + 36 <= F_) && (t0 >= 4) && (t0 + 36 <= T_);

    // ---- stage 0: load both channels into SX (float2), halo 4 ----
    if (interior) {
#pragma unroll
        for (int p = 0; p < 5; p++) {
            int r  = ty + 8 * p;
            const size_t o0 = (size_t)(f0 - 4 + r) * T_ + (t0 - 4);
            float2* row = SX + r * 41;
            row[tx] = make_float2(__ldg(img0 + o0 + tx), __ldg(img1 + o0 + tx));
            if (tx < 8)
                row[32 + tx] = make_float2(__ldg(img0 + o0 + 32 + tx),
                                           __ldg(img1 + o0 + 32 + tx));
        }
    } else {
#pragma unroll
        for (int p = 0; p < 5; p++) {
            int r  = ty + 8 * p;
            int gfr = f0 - 4 + r;
            float2* row = SX + r * 41;
            {
                int gt = t0 - 4 + tx;
                float2 v = make_float2(0.f, 0.f);
                if ((unsigned)gfr < F_ && (unsigned)gt < T_) {
                    size_t o = (size_t)gfr * T_ + gt;
                    v.x = __ldg(img0 + o);
                    v.y = __ldg(img1 + o);
                }
                row[tx] = v;
            }
            if (tx < 8) {
                int gt = t0 + 28 + tx;
                float2 v = make_float2(0.f, 0.f);
                if ((unsigned)gfr < F_ && (unsigned)gt < T_) {
                    size_t o = (size_t)gfr * T_ + gt;
                    v.x = __ldg(img0 + o);
                    v.y = __ldg(img1 + o);
                }
                row[32 + tx] = v;
            }
        }
    }
    __syncthreads();

    // ---- stage 0b: harmonic |2*v3 - v0 - v6| (channel pair) ----
    float2 harm[4];
    {
        float2 v[10];
#pragma unroll
        for (int j = 0; j < 10; j++)
            v[j] = SX[(4 * ty + 1 + j) * 41 + (tx + 4)];
#pragma unroll
        for (int k = 0; k < 4; k++) {
            harm[k].x = fabsf(2.f * v[k + 3].x - v[k].x - v[k + 6].x);
            harm[k].y = fabsf(2.f * v[k + 3].y - v[k].y - v[k + 6].y);
        }
    }

    // ---- stage 1: sobel + UU(fp16) + six F planes ----
    if (interior) stage1_run<false>(smb, SX, tid, t0, f0);
    else          stage1_run<true >(smb, SX, tid, t0, f0);
    __syncthreads();   // SX dead; HT overlays it from here

    const int rb = 4 * ty;
    // vertical 5-tap fully in half2; convert only the 4 results
#define VLOAD(pidx, s)                                                         \
    {                                                                          \
        const char* hb = smb + HT_B(pidx) + (tx * 36 + rb) * 4;                \
        uint4 qa = *(const uint4*)hb;                                          \
        uint4 qb = *(const uint4*)(hb + 16);                                   \
        __half2 r0 = g5h(H2C(qa.x), H2C(qa.y), H2C(qa.z), H2C(qa.w), H2C(qb.x)); \
        __half2 r1 = g5h(H2C(qa.y), H2C(qa.z), H2C(qa.w), H2C(qb.x), H2C(qb.y)); \
        __half2 r2 = g5h(H2C(qa.z), H2C(qa.w), H2C(qb.x), H2C(qb.y), H2C(qb.z)); \
        __half2 r3 = g5h(H2C(qa.w), H2C(qb.x), H2C(qb.y), H2C(qb.z), H2C(qb.w)); \
        s[0] = __half22float2(r0);                                             \
        s[1] = __half22float2(r1);                                             \
        s[2] = __half22float2(r2);                                             \
        s[3] = __half22float2(r3);                                             \
    }

    // ================= group 1: entropy (P0,P1,P2) =================
    {
        float2 sxx[4], syy[4], sxy[4];
        hpass3(smb, FP_B(0), tx, ty);
        __syncthreads();
        VLOAD(0, sxx) VLOAD(1, syy) VLOAD(2, sxy)
#pragma unroll
        for (int k = 0; k < 4; k++) {
            float e2 = 0.f;
#pragma unroll
            for (int ch = 0; ch < 2; ch++) {
                float vxx = ch ? sxx[k].y : sxx[k].x;
                float vyy = ch ? syy[k].y : syy[k].x;
                float vxy = ch ? sxy[k].y : sxy[k].x;
                float trace = vxx + vyy;
                float dif   = vxx - vyy;
                float disc  = sqrtf(fmaf(dif, dif, 4.f * vxy * vxy) + EPSV);
                float l1 = fmaxf((trace + disc) * 0.5f, EPSV);
                float l2 = fmaxf((trace - disc) * 0.5f, EPSV);
                float sinv = __fdividef(1.f, l1 + l2 + EPSV);
                float p1 = l1 * sinv, p2 = l2 * sinv;
                float ent = -(p1 * __logf(p1 + EPSV) + p2 * __logf(p2 + EPSV)) * 1.4426950408889634f;
                e2 += fminf(fmaxf(ent, 0.f), 1.f);
            }
            obase[k * T_] = e2 * 0.5f;
        }
    }
    __syncthreads();

    // ============ group 2: harmonic/temporal/spectral (P6,P7,P8) ============
    {
        float2 s6[4], s7[4], s8[4];
        hpass3(smb, FP_B(3), tx, ty);
        __syncthreads();
        VLOAD(0, s6) VLOAD(1, s7) VLOAD(2, s8)
#pragma unroll
        for (int k = 0; k < 4; k++) {
            float h0 = fminf(fmaxf(__fdividef(harm[k].x, s6[k].x + EPSV), 0.f), 1.f);
            float h1 = fminf(fmaxf(__fdividef(harm[k].y, s6[k].y + EPSV), 0.f), 1.f);
            obase[3 * MSTR + k * T_] = (h0 + h1) * 0.5f;
            float t0v = fminf(fmaxf(s7[k].x, 0.f), 1.f);
            float t1v = fminf(fmaxf(s7[k].y, 0.f), 1.f);
            obase[4 * MSTR + k * T_] = (t0v + t1v) * 0.5f;
            float sp0 = fminf(fmaxf(s8[k].x, 0.f), 1.f);
            float sp1 = fminf(fmaxf(s8[k].y, 0.f), 1.f);
            obase[5 * MSTR + k * T_] = (sp0 + sp1) * 0.5f;
        }
    }
    __syncthreads();

    // ============ group 3: alignment (UU) + curvature (FB overlays P0 slot) ============
    {
        // (i) curvature field at 36x36 -> FB (f32x2 math on fp16 UU data)
        int cc = tid % 36;
        int q  = tid / 36;
        if (q < 6) {
            const float2 two = make_float2(2.f, 2.f);
            const float2 e8  = make_float2(0.125f, 0.125f);
            const float2 ep2 = make_float2(EPSV, EPSV);
            int fr = 6 * q;
            int frN = fr + 6;
            const uint2* up = (const uint2*)(smb + UU_B) + fr * 39 + cc;
            uint2 U0 = up[0], U1 = up[1], U2 = up[2];
            up += 39;
            uint2 V0r = up[0], V1r = up[1], V2r = up[2];
            float2 A0x = h2f(U0.x), A0y = h2f(U0.y);
            float2 A1x = h2f(U1.x), A1y = h2f(U1.y);
            float2 A2x = h2f(U2.x), A2y = h2f(U2.y);
            float2 B0x = h2f(V0r.x), B0y = h2f(V0r.y);
            float2 B1x = h2f(V1r.x), B1y = h2f(V1r.y);
            float2 B2x = h2f(V2r.x), B2y = h2f(V2r.y);
            bool inc = !interior ? ((unsigned)(t0 - 2 + cc) < T_) : true;
            for (; fr < frN; fr++) {
                const uint2* cp = (const uint2*)(smb + UU_B) + (fr + 2) * 39 + cc;
                uint2 W0r = cp[0], W1r = cp[1], W2r = cp[2];
                float2 C0x = h2f(W0r.x), C0y = h2f(W0r.y);
                float2 C1x = h2f(W1r.x), C1y = h2f(W1r.y);
                float2 C2x = h2f(W2r.x), C2y = h2f(W2r.y);
                float2 P5 = make_float2(0.f, 0.f);
                if (inc && (interior || (unsigned)(f0 - 2 + fr) < F_)) {
                    float2 dudx = f2mul(e8, f2fma(two, f2sub(B2x, B0x),
                                      f2add(f2sub(A2x, A0x), f2sub(C2x, C0x))));
                    float2 dvdx = f2mul(e8, f2fma(two, f2sub(B2y, B0y),
                                      f2add(f2sub(A2y, A0y), f2sub(C2y, C0y))));
                    float2 dudy = f2mul(e8, f2fma(two, f2sub(C1x, A1x),
                                      f2add(f2sub(C0x, A0x), f2sub(C2x, A2x))));
                    float2 dvdy = f2mul(e8, f2fma(two, f2sub(C1y, A1y),
                                      f2add(f2sub(C0y, A0y), f2sub(C2y, A2y))));
                    float2 c2 = f2fma(dudx, dudx, f2fma(dudy, dudy,
                                f2fma(dvdx, dvdx, f2fma(dvdy, dvdy, ep2))));
                    P5.x = sqrtf(c2.x);
                    P5.y = sqrtf(c2.y);
                }
                *(unsigned*)(smb + FB_B + (fr * 36 + cc) * 4) = f2h(P5);
                A0x = B0x; A1x = B1x; A2x = B2x;
                A0y = B0y; A1y = B1y; A2y = B2y;
                B0x = C0x; B1x = C1x; B2x = C2x;
                B0y = C0y; B1y = C1y; B2y = C2y;
            }
        }
        // (ii) horizontal pass for ux,uy directly from UU -> HT0, HT1 (independent of FB)
        int c0 = 4 * ty;
#pragma unroll
        for (int it = 0; it < 2; it++) {
            int r = (it == 0) ? tx : 32 + tx;
            if (it == 1 && tx >= 4) break;
            const char* ub = smb + UU_B + ((r + 1) * 39 + (c0 + 1)) * 8;
            uint2 u0 = *(const uint2*)(ub);
            uint2 u1 = *(const uint2*)(ub + 8);
            uint2 u2 = *(const uint2*)(ub + 16);
            uint2 u3 = *(const uint2*)(ub + 24);
            uint2 u4 = *(const uint2*)(ub + 32);
            uint2 u5 = *(const uint2*)(ub + 40);
            uint2 u6 = *(const uint2*)(ub + 48);
            uint2 u7 = *(const uint2*)(ub + 56);
#define HX(j) (*(__half2*)&u##j.x)
#define HY(j) (*(__half2*)&u##j.y)
            __half2 x0 = g5h(HX(0), HX(1), HX(2), HX(3), HX(4));
            __half2 x1 = g5h(HX(1), HX(2), HX(3), HX(4), HX(5));
            __half2 x2 = g5h(HX(2), HX(3), HX(4), HX(5), HX(6));
            __half2 x3 = g5h(HX(3), HX(4), HX(5), HX(6), HX(7));
            __half2 y0 = g5h(HY(0), HY(1), HY(2), HY(3), HY(4));
            __half2 y1 = g5h(HY(1), HY(2), HY(3), HY(4), HY(5));
            __half2 y2 = g5h(HY(2), HY(3), HY(4), HY(5), HY(6));
            __half2 y3 = g5h(HY(3), HY(4), HY(5), HY(6), HY(7));
#undef HX
#undef HY
            char* hb0 = smb + HT_B(0) + (c0 * 36 + r) * 4;
            *(unsigned*)(hb0)       = *(unsigned*)&x0;
            *(unsigned*)(hb0 + 144) = *(unsigned*)&x1;
            *(unsigned*)(hb0 + 288) = *(unsigned*)&x2;
            *(unsigned*)(hb0 + 432) = *(unsigned*)&x3;
            char* hb1 = smb + HT_B(1) + (c0 * 36 + r) * 4;
            *(unsigned*)(hb1)       = *(unsigned*)&y0;
            *(unsigned*)(hb1 + 144) = *(unsigned*)&y1;
            *(unsigned*)(hb1 + 288) = *(unsigned*)&y2;
            *(unsigned*)(hb1 + 432) = *(unsigned*)&y3;
        }
    }
    __syncthreads();                    // FB complete + HT0/1 complete
    hpass_f(smb, FB_B, HT_B(2), tx, ty);
    __syncthreads();
    {
        float2 sux[4], suy[4], scv[4];
        VLOAD(0, sux) VLOAD(1, suy) VLOAD(2, scv)
#pragma unroll
        for (int k = 0; k < 4; k++) {
            float a0 = fminf(sqrtf(fmaf(sux[k].x, sux[k].x, fmaf(suy[k].x, suy[k].x, EPSV))), 1.f);
            float a1 = fminf(sqrtf(fmaf(sux[k].y, sux[k].y, fmaf(suy[k].y, suy[k].y, EPSV))), 1.f);
            obase[MSTR + k * T_] = (a0 + a1) * 0.5f;
            obase[2 * MSTR + k * T_] = (scv[k].x + scv[k].y) * 0.5f;
        }
    }
#undef VLOAD
}

extern "C" void kernel_launch(void* const* d_in, const int* in_sizes, int n_in,
                              void* d_out, int out_size)
{
    const float* spec = (const float*)d_in[0];
    float* out = (float*)d_out;

    cudaFuncSetAttribute(asa_kernel, cudaFuncAttributeMaxDynamicSharedMemorySize, SMEM_BYTES);

    dim3 grid(T_ / 32, F_ / 32, B_);   // 4096 CTAs
    dim3 block(32, 8, 1);
    asa_kernel<<<grid, block, SMEM_BYTES>>>(spec, out);
}

// round 12
// speedup vs baseline: 1.5034x; 1.5034x over previous
#include <cuda_runtime.h>
#include <cuda_fp16.h>

#define B_ 8
#define C_ 2
#define F_ 256
#define T_ 2048
#define EPSV 1e-10f

// gaussian 1D (sigma=1, ws=5) separable factor, symmetric [W0,W1,W2,W1,W0]
#define W0 0.054488684548904895f
#define W1 0.24420134200323332f
#define W2 0.4026199468917436f

// ---- smem byte layout (channel-packed, 4 CTA/SM) ----
// HT scratch: 3 transposed planes [col 0..31][row 0..35] half2, col pitch 36 half2
//   HT_B(p) = p*4608 -> [0, 13824)
// SX float2 40x41 = 13120 overlays [0,13120) (dead after stage 1)
// UU @13824: 38x39 x uint2{half2 ux, half2 uy} = 11856 -> [13824, 25680)
// F planes @25680: 6 planes half2 36x36 pitch 36 (P0,P1,P2,P6,P7,P8), 5184 each -> 56784
// FB (curvature) overlays FP(0) after entropy group consumed it.
#define HT_B(p) ((p) * 4608)
#define UU_B    13824
#define FP_B(q) (25680 + (q) * 5184)
#define FB_B    FP_B(0)
#define SMEM_BYTES 56784

#define W0H __float2half2_rn(W0)
#define W1H __float2half2_rn(W1)
#define W2H __float2half2_rn(W2)

// ---- f32x2 packed helpers (sm_103a) ----
__device__ __forceinline__ float2 f2add(float2 a, float2 b) {
    unsigned long long ua = *(unsigned long long*)&a, ub = *(unsigned long long*)&b, ur;
    asm("add.rn.f32x2 %0, %1, %2;" : "=l"(ur) : "l"(ua), "l"(ub));
    return *(float2*)&ur;
}
__device__ __forceinline__ float2 f2mul(float2 a, float2 b) {
    unsigned long long ua = *(unsigned long long*)&a, ub = *(unsigned long long*)&b, ur;
    asm("mul.rn.f32x2 %0, %1, %2;" : "=l"(ur) : "l"(ua), "l"(ub));
    return *(float2*)&ur;
}
__device__ __forceinline__ float2 f2fma(float2 a, float2 b, float2 c) {
    unsigned long long ua = *(unsigned long long*)&a, ub = *(unsigned long long*)&b,
                       uc = *(unsigned long long*)&c, ur;
    asm("fma.rn.f32x2 %0, %1, %2, %3;" : "=l"(ur) : "l"(ua), "l"(ub), "l"(uc));
    return *(float2*)&ur;
}
__device__ __forceinline__ float2 f2sub(float2 a, float2 b) {
    return f2fma(b, make_float2(-1.f, -1.f), a);
}
__device__ __forceinline__ __half2 g5h(__half2 a, __half2 b, __half2 c, __half2 d, __half2 e) {
    return __hfma2(W0H, __hadd2(a, e), __hfma2(W1H, __hadd2(b, d), __hmul2(W2H, c)));
}
__device__ __forceinline__ float2 h2f(unsigned u) {
    __half2 h = *(__half2*)&u;
    return __half22float2(h);
}
__device__ __forceinline__ unsigned f2h(float2 v) {
    __half2 h = __floats2half2_rn(v.x, v.y);
    return *(unsigned*)&h;
}
#define H2C(u) (*(__half2*)&(u))

// single-plane horizontal 5-tap over an F plane (pitch 36 half2) -> transposed HT plane
// (per-plane dispatch: narrow live window — the flattened variant spilled, see R11)
__device__ __forceinline__ void hpass_f(char* smb, int fsrc_b, int htp_b, int tx, int ty) {
    int c0 = 4 * ty;
#pragma unroll
    for (int it = 0; it < 2; it++) {
        int r = (it == 0) ? tx : 32 + tx;
        if (it == 1 && tx >= 4) break;
        const char* fb = smb + fsrc_b + (r * 36 + c0) * 4;
        uint4 qa = *(const uint4*)fb;
        uint4 qb = *(const uint4*)(fb + 16);
        __half2 h0 = H2C(qa.x), h1 = H2C(qa.y), h2 = H2C(qa.z), h3 = H2C(qa.w);
        __half2 h4 = H2C(qb.x), h5 = H2C(qb.y), h6 = H2C(qb.z), h7 = H2C(qb.w);
        __half2 o0 = g5h(h0, h1, h2, h3, h4);
        __half2 o1 = g5h(h1, h2, h3, h4, h5);
        __half2 o2 = g5h(h2, h3, h4, h5, h6);
        __half2 o3 = g5h(h3, h4, h5, h6, h7);
        char* hb = smb + htp_b + (c0 * 36 + r) * 4;
        *(unsigned*)(hb)       = *(unsigned*)&o0;
        *(unsigned*)(hb + 144) = *(unsigned*)&o1;
        *(unsigned*)(hb + 288) = *(unsigned*)&o2;
        *(unsigned*)(hb + 432) = *(unsigned*)&o3;
    }
}

// ---- stage 1 specialized on border checking (CHK=false for interior CTAs) ----
template<bool CHK>
__device__ __forceinline__ void stage1_run(char* smb, const float2* SX,
                                           int tid, int t0, int f0)
{
    const float2 two = make_float2(2.f, 2.f);
    const float2 e8  = make_float2(0.125f, 0.125f);
    const float2 ep2 = make_float2(EPSV, EPSV);
    int cc = tid % 38;
    int q  = tid / 38;
    if (q < 6) {
        int r  = 7 * q;
        int rN = min(r + 7, 38);
        const float2* p = SX + r * 41 + cc;
        float2 a0 = p[0], a1 = p[1], a2 = p[2];
        p += 41;
        float2 b0 = p[0], b1 = p[1], b2 = p[2];
        bool inc = !CHK || (unsigned)(t0 - 3 + cc) < T_;
        for (; r < rN; r++) {
            const float2* pc = SX + (r + 2) * 41 + cc;
            float2 c0v = pc[0], c1v = pc[1], c2v = pc[2];
            float2 gtv = f2mul(e8, f2fma(two, f2sub(b2, b0),
                              f2add(f2sub(a2, a0), f2sub(c2v, c0v))));
            float2 gfv = f2mul(e8, f2fma(two, f2sub(c1v, a1),
                              f2add(f2sub(c0v, a0), f2sub(c2v, a2))));
            bool in = !CHK || (inc && ((unsigned)(f0 - 3 + r) < F_));
            float2 ux2 = make_float2(0.f, 0.f), uy2 = ux2;
            float2 txe = ux2;
            if (in) {
                txe = f2add(gtv, ep2);
                float2 r2v = f2fma(gfv, gfv, f2mul(txe, txe));
                float2 rin;
                rin.x = rsqrtf(fmaxf(r2v.x, 1e-30f));
                rin.y = rsqrtf(fmaxf(r2v.y, 1e-30f));
                ux2 = f2mul(txe, rin);
                uy2 = f2mul(gfv, rin);
            } else {
                gfv = make_float2(0.f, 0.f);
                gtv = gfv;
            }
            *(uint2*)(smb + UU_B + (r * 39 + cc) * 8) =
                make_uint2(f2h(ux2), f2h(uy2));
            if (r >= 1 && r <= 36 && cc >= 1 && cc <= 36) {
                int o = (r - 1) * 36 + (cc - 1);
                // mag2/r2 = 1 + O(eps/mag2): tensor fields collapse to raw products
                float2 P0 = f2mul(txe, txe);
                float2 P1 = f2mul(gfv, gfv);
                float2 P2 = f2mul(txe, gfv);
                float2 P6 = f2mul(b1, b1);       // b1 zero-filled at borders
                float2 P7, P8;
                if (in) {
                    P7.x = __fdividef(1.f, 1.f + fabsf(gtv.x));
                    P7.y = __fdividef(1.f, 1.f + fabsf(gtv.y));
                } else {
                    P7 = make_float2(0.f, 0.f);
                }
                P8.x = fabsf(gfv.x);
                P8.y = fabsf(gfv.y);
                *(unsigned*)(smb + FP_B(0) + o * 4) = f2h(P0);
                *(unsigned*)(smb + FP_B(1) + o * 4) = f2h(P1);
                *(unsigned*)(smb + FP_B(2) + o * 4) = f2h(P2);
                *(unsigned*)(smb + FP_B(3) + o * 4) = f2h(P6);
                *(unsigned*)(smb + FP_B(4) + o * 4) = f2h(P7);
                *(unsigned*)(smb + FP_B(5) + o * 4) = f2h(P8);
            }
            a0 = b0; a1 = b1; a2 = b2;
            b0 = c0v; b1 = c1v; b2 = c2v;
        }
    }
}

__global__ void __launch_bounds__(256, 4)
asa_kernel(const float* __restrict__ spec, float* __restrict__ out)
{
    extern __shared__ float sm[];
    char*   smb = (char*)sm;
    float2* SX  = (float2*)smb;   // 40 x 41 channel pair (overlaid by HT later)

    const int tx  = threadIdx.x;   // 0..31
    const int ty  = threadIdx.y;   // 0..7
    const int tid = ty * 32 + tx;
    const int t0  = blockIdx.x * 32;
    const int f0  = blockIdx.y * 32;
    const int b   = blockIdx.z;

    const size_t FT   = (size_t)F_ * T_;
    const size_t MSTR = (size_t)B_ * FT;
    const float* img0 = spec + (size_t)(b * 2) * FT;
    const float* img1 = img0 + FT;
    float* obase = out + (size_t)b * FT + (size_t)(f0 + 4 * ty) * T_ + t0 + tx;

    const bool interior = (f0 >= 4) && (f0 + 36 <= F_) && (t0 >= 4) && (t0 + 36 <= T_);

    // ---- stage 0: load both channels into SX (float2), halo 4 ----
    if (interior) {
#pragma unroll
        for (int p = 0; p < 5; p++) {
            int r  = ty + 8 * p;
            const size_t o0 = (size_t)(f0 - 4 + r) * T_ + (t0 - 4);
            float2* row = SX + r * 41;
            row[tx] = make_float2(__ldg(img0 + o0 + tx), __ldg(img1 + o0 + tx));
            if (tx < 8)
                row[32 + tx] = make_float2(__ldg(img0 + o0 + 32 + tx),
                                           __ldg(img1 + o0 + 32 + tx));
        }
    } else {
#pragma unroll
        for (int p = 0; p < 5; p++) {
            int r  = ty + 8 * p;
            int gfr = f0 - 4 + r;
            float2* row = SX + r * 41;
            {
                int gt = t0 - 4 + tx;
                float2 v = make_float2(0.f, 0.f);
                if ((unsigned)gfr < F_ && (unsigned)gt < T_) {
                    size_t o = (size_t)gfr * T_ + gt;
                    v.x = __ldg(img0 + o);
                    v.y = __ldg(img1 + o);
                }
                row[tx] = v;
            }
            if (tx < 8) {
                int gt = t0 + 28 + tx;
                float2 v = make_float2(0.f, 0.f);
                if ((unsigned)gfr < F_ && (unsigned)gt < T_) {
                    size_t o = (size_t)gfr * T_ + gt;
                    v.x = __ldg(img0 + o);
                    v.y = __ldg(img1 + o);
                }
                row[32 + tx] = v;
            }
        }
    }
    __syncthreads();

    // ---- stage 0b: harmonic |2*v3 - v0 - v6| (channel pair) ----
    float2 harm[4];
    {
        float2 v[10];
#pragma unroll
        for (int j = 0; j < 10; j++)
            v[j] = SX[(4 * ty + 1 + j) * 41 + (tx + 4)];
#pragma unroll
        for (int k = 0; k < 4; k++) {
            harm[k].x = fabsf(2.f * v[k + 3].x - v[k].x - v[k + 6].x);
            harm[k].y = fabsf(2.f * v[k + 3].y - v[k].y - v[k + 6].y);
        }
    }

    // ---- stage 1: sobel + UU(fp16) + six F planes ----
    if (interior) stage1_run<false>(smb, SX, tid, t0, f0);
    else          stage1_run<true >(smb, SX, tid, t0, f0);
    __syncthreads();   // SX dead; HT overlays it from here

    const int rb = 4 * ty;
    // vertical 5-tap fully in half2; convert only the 4 results
#define VLOAD(pidx, s)                                                         \
    {                                                                          \
        const char* hb = smb + HT_B(pidx) + (tx * 36 + rb) * 4;                \
        uint4 qa = *(const uint4*)hb;                                          \
        uint4 qb = *(const uint4*)(hb + 16);                                   \
        __half2 r0 = g5h(H2C(qa.x), H2C(qa.y), H2C(qa.z), H2C(qa.w), H2C(qb.x)); \
        __half2 r1 = g5h(H2C(qa.y), H2C(qa.z), H2C(qa.w), H2C(qb.x), H2C(qb.y)); \
        __half2 r2 = g5h(H2C(qa.z), H2C(qa.w), H2C(qb.x), H2C(qb.y), H2C(qb.z)); \
        __half2 r3 = g5h(H2C(qa.w), H2C(qb.x), H2C(qb.y), H2C(qb.z), H2C(qb.w)); \
        s[0] = __half22float2(r0);                                             \
        s[1] = __half22float2(r1);                                             \
        s[2] = __half22float2(r2);                                             \
        s[3] = __half22float2(r3);                                             \
    }

    // ================= group 1: entropy (P0,P1,P2) =================
    {
        float2 sxx[4], syy[4], sxy[4];
        hpass_f(smb, FP_B(0), HT_B(0), tx, ty);
        hpass_f(smb, FP_B(1), HT_B(1), tx, ty);
        hpass_f(smb, FP_B(2), HT_B(2), tx, ty);
        __syncthreads();
        VLOAD(0, sxx) VLOAD(1, syy) VLOAD(2, sxy)
#pragma unroll
        for (int k = 0; k < 4; k++) {
            float e2 = 0.f;
#pragma unroll
            for (int ch = 0; ch < 2; ch++) {
                float vxx = ch ? sxx[k].y : sxx[k].x;
                float vyy = ch ? syy[k].y : syy[k].x;
                float vxy = ch ? sxy[k].y : sxy[k].x;
                float trace = vxx + vyy;
                float dif   = vxx - vyy;
                float disc  = sqrtf(fmaf(dif, dif, 4.f * vxy * vxy) + EPSV);
                float l1 = fmaxf((trace + disc) * 0.5f, EPSV);
                float l2 = fmaxf((trace - disc) * 0.5f, EPSV);
                float sinv = __fdividef(1.f, l1 + l2 + EPSV);
                float p1 = l1 * sinv, p2 = l2 * sinv;
                float ent = -(p1 * __logf(p1 + EPSV) + p2 * __logf(p2 + EPSV)) * 1.4426950408889634f;
                e2 += fminf(fmaxf(ent, 0.f), 1.f);
            }
            obase[k * T_] = e2 * 0.5f;
        }
    }
    __syncthreads();

    // ============ group 2: harmonic/temporal/spectral (P6,P7,P8) ============
    {
        float2 s6[4], s7[4], s8[4];
        hpass_f(smb, FP_B(3), HT_B(0), tx, ty);
        hpass_f(smb, FP_B(4), HT_B(1), tx, ty);
        hpass_f(smb, FP_B(5), HT_B(2), tx, ty);
        __syncthreads();
        VLOAD(0, s6) VLOAD(1, s7) VLOAD(2, s8)
#pragma unroll
        for (int k = 0; k < 4; k++) {
            float h0 = fminf(fmaxf(__fdividef(harm[k].x, s6[k].x + EPSV), 0.f), 1.f);
            float h1 = fminf(fmaxf(__fdividef(harm[k].y, s6[k].y + EPSV), 0.f), 1.f);
            obase[3 * MSTR + k * T_] = (h0 + h1) * 0.5f;
            float t0v = fminf(fmaxf(s7[k].x, 0.f), 1.f);
            float t1v = fminf(fmaxf(s7[k].y, 0.f), 1.f);
            obase[4 * MSTR + k * T_] = (t0v + t1v) * 0.5f;
            float sp0 = fminf(fmaxf(s8[k].x, 0.f), 1.f);
            float sp1 = fminf(fmaxf(s8[k].y, 0.f), 1.f);
            obase[5 * MSTR + k * T_] = (sp0 + sp1) * 0.5f;
        }
    }
    __syncthreads();

    // ============ group 3: alignment (UU) + curvature (FB overlays P0 slot) ============
    {
        // (i) curvature field at 36x36 -> FB (f32x2 math on fp16 UU data)
        int cc = tid % 36;
        int q  = tid / 36;
        if (q < 6) {
            const float2 two = make_float2(2.f, 2.f);
            const float2 e8  = make_float2(0.125f, 0.125f);
            const float2 ep2 = make_float2(EPSV, EPSV);
            int fr = 6 * q;
            int frN = fr + 6;
            const uint2* up = (const uint2*)(smb + UU_B) + fr * 39 + cc;
            uint2 U0 = up[0], U1 = up[1], U2 = up[2];
            up += 39;
            uint2 V0r = up[0], V1r = up[1], V2r = up[2];
            float2 A0x = h2f(U0.x), A0y = h2f(U0.y);
            float2 A1x = h2f(U1.x), A1y = h2f(U1.y);
            float2 A2x = h2f(U2.x), A2y = h2f(U2.y);
            float2 B0x = h2f(V0r.x), B0y = h2f(V0r.y);
            float2 B1x = h2f(V1r.x), B1y = h2f(V1r.y);
            float2 B2x = h2f(V2r.x), B2y = h2f(V2r.y);
            bool inc = !interior ? ((unsigned)(t0 - 2 + cc) < T_) : true;
            for (; fr < frN; fr++) {
                const uint2* cp = (const uint2*)(smb + UU_B) + (fr + 2) * 39 + cc;
                uint2 W0r = cp[0], W1r = cp[1], W2r = cp[2];
                float2 C0x = h2f(W0r.x), C0y = h2f(W0r.y);
                float2 C1x = h2f(W1r.x), C1y = h2f(W1r.y);
                float2 C2x = h2f(W2r.x), C2y = h2f(W2r.y);
                float2 P5 = make_float2(0.f, 0.f);
                if (inc && (interior || (unsigned)(f0 - 2 + fr) < F_)) {
                    float2 dudx = f2mul(e8, f2fma(two, f2sub(B2x, B0x),
                                      f2add(f2sub(A2x, A0x), f2sub(C2x, C0x))));
                    float2 dvdx = f2mul(e8, f2fma(two, f2sub(B2y, B0y),
                                      f2add(f2sub(A2y, A0y), f2sub(C2y, C0y))));
                    float2 dudy = f2mul(e8, f2fma(two, f2sub(C1x, A1x),
                                      f2add(f2sub(C0x, A0x), f2sub(C2x, A2x))));
                    float2 dvdy = f2mul(e8, f2fma(two, f2sub(C1y, A1y),
                                      f2add(f2sub(C0y, A0y), f2sub(C2y, A2y))));
                    float2 c2 = f2fma(dudx, dudx, f2fma(dudy, dudy,
                                f2fma(dvdx, dvdx, f2fma(dvdy, dvdy, ep2))));
                    P5.x = sqrtf(c2.x);
                    P5.y = sqrtf(c2.y);
                }
                *(unsigned*)(smb + FB_B + (fr * 36 + cc) * 4) = f2h(P5);
                A0x = B0x; A1x = B1x; A2x = B2x;
                A0y = B0y; A1y = B1y; A2y = B2y;
                B0x = C0x; B1x = C1x; B2x = C2x;
                B0y = C0y; B1y = C1y; B2y = C2y;
            }
        }
        // (ii) horizontal pass for ux,uy directly from UU -> HT0, HT1 (independent of FB)
        int c0 = 4 * ty;
#pragma unroll
        for (int it = 0; it < 2; it++) {
            int r = (it == 0) ? tx : 32 + tx;
            if (it == 1 && tx >= 4) break;
            const char* ub = smb + UU_B + ((r + 1) * 39 + (c0 + 1)) * 8;
            uint2 u0 = *(const uint2*)(ub);
            uint2 u1 = *(const uint2*)(ub + 8);
            uint2 u2 = *(const uint2*)(ub + 16);
            uint2 u3 = *(const uint2*)(ub + 24);
            uint2 u4 = *(const uint2*)(ub + 32);
            uint2 u5 = *(const uint2*)(ub + 40);
            uint2 u6 = *(const uint2*)(ub + 48);
            uint2 u7 = *(const uint2*)(ub + 56);
#define HX(j) (*(__half2*)&u##j.x)
#define HY(j) (*(__half2*)&u##j.y)
            __half2 x0 = g5h(HX(0), HX(1), HX(2), HX(3), HX(4));
            __half2 x1 = g5h(HX(1), HX(2), HX(3), HX(4), HX(5));
            __half2 x2 = g5h(HX(2), HX(3), HX(4), HX(5), HX(6));
            __half2 x3 = g5h(HX(3), HX(4), HX(5), HX(6), HX(7));
            __half2 y0 = g5h(HY(0), HY(1), HY(2), HY(3), HY(4));
            __half2 y1 = g5h(HY(1), HY(2), HY(3), HY(4), HY(5));
            __half2 y2 = g5h(HY(2), HY(3), HY(4), HY(5), HY(6));
            __half2 y3 = g5h(HY(3), HY(4), HY(5), HY(6), HY(7));
#undef HX
#undef HY
            char* hb0 = smb + HT_B(0) + (c0 * 36 + r) * 4;
            *(unsigned*)(hb0)       = *(unsigned*)&x0;
            *(unsigned*)(hb0 + 144) = *(unsigned*)&x1;
            *(unsigned*)(hb0 + 288) = *(unsigned*)&x2;
            *(unsigned*)(hb0 + 432) = *(unsigned*)&x3;
            char* hb1 = smb + HT_B(1) + (c0 * 36 + r) * 4;
            *(unsigned*)(hb1)       = *(unsigned*)&y0;
            *(unsigned*)(hb1 + 144) = *(unsigned*)&y1;
            *(unsigned*)(hb1 + 288) = *(unsigned*)&y2;
            *(unsigned*)(hb1 + 432) = *(unsigned*)&y3;
        }
    }
    __syncthreads();                    // FB complete + HT0/1 complete
    hpass_f(smb, FB_B, HT_B(2), tx, ty);
    __syncthreads();
    {
        float2 sux[4], suy[4], scv[4];
        VLOAD(0, sux) VLOAD(1, suy) VLOAD(2, scv)
#pragma unroll
        for (int k = 0; k < 4; k++) {
            float a0 = fminf(sqrtf(fmaf(sux[k].x, sux[k].x, fmaf(suy[k].x, suy[k].x, EPSV))), 1.f);
            float a1 = fminf(sqrtf(fmaf(sux[k].y, sux[k].y, fmaf(suy[k].y, suy[k].y, EPSV))), 1.f);
            obase[MSTR + k * T_] = (a0 + a1) * 0.5f;
            obase[2 * MSTR + k * T_] = (scv[k].x + scv[k].y) * 0.5f;
        }
    }
#undef VLOAD
}

extern "C" void kernel_launch(void* const* d_in, const int* in_sizes, int n_in,
                              void* d_out, int out_size)
{
    const float* spec = (const float*)d_in[0];
    float* out = (float*)d_out;

    cudaFuncSetAttribute(asa_kernel, cudaFuncAttributeMaxDynamicSharedMemorySize, SMEM_BYTES);

    dim3 grid(T_ / 32, F_ / 32, B_);   // 4096 CTAs
    dim3 block(32, 8, 1);
    asa_kernel<<<grid, block, SMEM_BYTES>>>(spec, out);
}

// round 13
// speedup vs baseline: 1.5946x; 1.0607x over previous
#include <cuda_runtime.h>
#include <cuda_fp16.h>

#define B_ 8
#define C_ 2
#define F_ 256
#define T_ 2048
#define EPSV 1e-10f

// gaussian 1D (sigma=1, ws=5) separable factor, symmetric [W0,W1,W2,W1,W0]
#define W0 0.054488684548904895f
#define W1 0.24420134200323332f
#define W2 0.4026199468917436f

// ---- smem byte layout (channel-packed, 4 CTA/SM) ----
// HT scratch: 3 transposed planes [col 0..31][row 0..35] half2, col pitch 36 half2
//   HT_B(p) = p*4608 -> [0, 13824)
// SX float2 40x41 = 13120 overlays [0,13120) (dead after stage 1)
// UU @13824: 38x39 x uint2{half2 ux, half2 uy} = 11856 -> [13824, 25680)
// F planes @25680: 6 planes half2 36x36 pitch 36 (P0,P1,P2,P6,P7,P8), 5184 each -> 56784
// FB (curvature) overlays FP(0) after entropy group consumed it.
#define HT_B(p) ((p) * 4608)
#define UU_B    13824
#define FP_B(q) (25680 + (q) * 5184)
#define FB_B    FP_B(0)
#define SMEM_BYTES 56784

#define W0H __float2half2_rn(W0)
#define W1H __float2half2_rn(W1)
#define W2H __float2half2_rn(W2)

// ---- f32x2 packed helpers (sm_103a) ----
__device__ __forceinline__ float2 f2add(float2 a, float2 b) {
    unsigned long long ua = *(unsigned long long*)&a, ub = *(unsigned long long*)&b, ur;
    asm("add.rn.f32x2 %0, %1, %2;" : "=l"(ur) : "l"(ua), "l"(ub));
    return *(float2*)&ur;
}
__device__ __forceinline__ float2 f2mul(float2 a, float2 b) {
    unsigned long long ua = *(unsigned long long*)&a, ub = *(unsigned long long*)&b, ur;
    asm("mul.rn.f32x2 %0, %1, %2;" : "=l"(ur) : "l"(ua), "l"(ub));
    return *(float2*)&ur;
}
__device__ __forceinline__ float2 f2fma(float2 a, float2 b, float2 c) {
    unsigned long long ua = *(unsigned long long*)&a, ub = *(unsigned long long*)&b,
                       uc = *(unsigned long long*)&c, ur;
    asm("fma.rn.f32x2 %0, %1, %2, %3;" : "=l"(ur) : "l"(ua), "l"(ub), "l"(uc));
    return *(float2*)&ur;
}
__device__ __forceinline__ float2 f2sub(float2 a, float2 b) {
    return f2fma(b, make_float2(-1.f, -1.f), a);
}
__device__ __forceinline__ __half2 g5h(__half2 a, __half2 b, __half2 c, __half2 d, __half2 e) {
    return __hfma2(W0H, __hadd2(a, e), __hfma2(W1H, __hadd2(b, d), __hmul2(W2H, c)));
}
__device__ __forceinline__ float2 h2f(unsigned u) {
    __half2 h = *(__half2*)&u;
    return __half22float2(h);
}
__device__ __forceinline__ unsigned f2h(float2 v) {
    __half2 h = __floats2half2_rn(v.x, v.y);
    return *(unsigned*)&h;
}
#define H2C(u) (*(__half2*)&(u))

// single-plane horizontal 5-tap over an F plane (pitch 36 half2) -> transposed HT plane
// (per-plane dispatch: narrow live window — the flattened variant spilled, see R11)
__device__ __forceinline__ void hpass_f(char* smb, int fsrc_b, int htp_b, int tx, int ty) {
    int c0 = 4 * ty;
#pragma unroll
    for (int it = 0; it < 2; it++) {
        int r = (it == 0) ? tx : 32 + tx;
        if (it == 1 && tx >= 4) break;
        const char* fb = smb + fsrc_b + (r * 36 + c0) * 4;
        uint4 qa = *(const uint4*)fb;
        uint4 qb = *(const uint4*)(fb + 16);
        __half2 h0 = H2C(qa.x), h1 = H2C(qa.y), h2 = H2C(qa.z), h3 = H2C(qa.w);
        __half2 h4 = H2C(qb.x), h5 = H2C(qb.y), h6 = H2C(qb.z), h7 = H2C(qb.w);
        __half2 o0 = g5h(h0, h1, h2, h3, h4);
        __half2 o1 = g5h(h1, h2, h3, h4, h5);
        __half2 o2 = g5h(h2, h3, h4, h5, h6);
        __half2 o3 = g5h(h3, h4, h5, h6, h7);
        char* hb = smb + htp_b + (c0 * 36 + r) * 4;
        *(unsigned*)(hb)       = *(unsigned*)&o0;
        *(unsigned*)(hb + 144) = *(unsigned*)&o1;
        *(unsigned*)(hb + 288) = *(unsigned*)&o2;
        *(unsigned*)(hb + 432) = *(unsigned*)&o3;
    }
}

// ---- stage 1 specialized on border checking (CHK=false for interior CTAs) ----
template<bool CHK>
__device__ __forceinline__ void stage1_run(char* smb, const float2* SX,
                                           int tid, int t0, int f0)
{
    const float2 two = make_float2(2.f, 2.f);
    const float2 e8  = make_float2(0.125f, 0.125f);
    const float2 ep2 = make_float2(EPSV, EPSV);
    int cc = tid % 38;
    int q  = tid / 38;
    if (q < 6) {
        int r  = 7 * q;
        int rN = min(r + 7, 38);
        const float2* p = SX + r * 41 + cc;
        float2 a0 = p[0], a1 = p[1], a2 = p[2];
        p += 41;
        float2 b0 = p[0], b1 = p[1], b2 = p[2];
        bool inc = !CHK || (unsigned)(t0 - 3 + cc) < T_;
        for (; r < rN; r++) {
            const float2* pc = SX + (r + 2) * 41 + cc;
            float2 c0v = pc[0], c1v = pc[1], c2v = pc[2];
            float2 gtv = f2mul(e8, f2fma(two, f2sub(b2, b0),
                              f2add(f2sub(a2, a0), f2sub(c2v, c0v))));
            float2 gfv = f2mul(e8, f2fma(two, f2sub(c1v, a1),
                              f2add(f2sub(c0v, a0), f2sub(c2v, a2))));
            bool in = !CHK || (inc && ((unsigned)(f0 - 3 + r) < F_));
            float2 ux2 = make_float2(0.f, 0.f), uy2 = ux2;
            float2 txe = ux2;
            if (in) {
                txe = f2add(gtv, ep2);
                float2 r2v = f2fma(gfv, gfv, f2mul(txe, txe));
                float2 rin;
                rin.x = rsqrtf(fmaxf(r2v.x, 1e-30f));
                rin.y = rsqrtf(fmaxf(r2v.y, 1e-30f));
                ux2 = f2mul(txe, rin);
                uy2 = f2mul(gfv, rin);
            } else {
                gfv = make_float2(0.f, 0.f);
                gtv = gfv;
            }
            *(uint2*)(smb + UU_B + (r * 39 + cc) * 8) =
                make_uint2(f2h(ux2), f2h(uy2));
            if (r >= 1 && r <= 36 && cc >= 1 && cc <= 36) {
                int o = (r - 1) * 36 + (cc - 1);
                // mag2/r2 = 1 + O(eps/mag2): tensor fields collapse to raw products
                float2 P0 = f2mul(txe, txe);
                float2 P1 = f2mul(gfv, gfv);
                float2 P2 = f2mul(txe, gfv);
                float2 P6 = f2mul(b1, b1);       // b1 zero-filled at borders
                float2 P7, P8;
                if (in) {
                    P7.x = __fdividef(1.f, 1.f + fabsf(gtv.x));
                    P7.y = __fdividef(1.f, 1.f + fabsf(gtv.y));
                } else {
                    P7 = make_float2(0.f, 0.f);
                }
                P8.x = fabsf(gfv.x);
                P8.y = fabsf(gfv.y);
                *(unsigned*)(smb + FP_B(0) + o * 4) = f2h(P0);
                *(unsigned*)(smb + FP_B(1) + o * 4) = f2h(P1);
                *(unsigned*)(smb + FP_B(2) + o * 4) = f2h(P2);
                *(unsigned*)(smb + FP_B(3) + o * 4) = f2h(P6);
                *(unsigned*)(smb + FP_B(4) + o * 4) = f2h(P7);
                *(unsigned*)(smb + FP_B(5) + o * 4) = f2h(P8);
            }
            a0 = b0; a1 = b1; a2 = b2;
            b0 = c0v; b1 = c1v; b2 = c2v;
        }
    }
}

// ---- group-3 curvature: half2 window (free reinterpret, half register footprint),
//      fp32 sqrt (MUFU path — h2sqrt was the R7 poison), interior-templated ----
template<bool CHK>
__device__ __forceinline__ void curv_run(char* smb, int tid, int t0, int f0)
{
    int cc = tid % 36;
    int q  = tid / 36;
    if (q >= 6) return;
    const __half2 twoh = __float2half2_rn(2.f);
    const __half2 e8h  = __float2half2_rn(0.125f);
    int fr  = 6 * q;
    int frN = fr + 6;
    const uint2* up = (const uint2*)(smb + UU_B) + fr * 39 + cc;
    uint2 U0 = up[0], U1 = up[1], U2 = up[2];
    up += 39;
    uint2 V0 = up[0], V1 = up[1], V2 = up[2];
    __half2 A0x = H2C(U0.x), A0y = H2C(U0.y);
    __half2 A1x = H2C(U1.x), A1y = H2C(U1.y);
    __half2 A2x = H2C(U2.x), A2y = H2C(U2.y);
    __half2 B0x = H2C(V0.x), B0y = H2C(V0.y);
    __half2 B1x = H2C(V1.x), B1y = H2C(V1.y);
    __half2 B2x = H2C(V2.x), B2y = H2C(V2.y);
    bool inc = !CHK || (unsigned)(t0 - 2 + cc) < T_;
    for (; fr < frN; fr++) {
        const uint2* cp = (const uint2*)(smb + UU_B) + (fr + 2) * 39 + cc;
        uint2 Wr0 = cp[0], Wr1 = cp[1], Wr2 = cp[2];
        __half2 C0x = H2C(Wr0.x), C0y = H2C(Wr0.y);
        __half2 C1x = H2C(Wr1.x), C1y = H2C(Wr1.y);
        __half2 C2x = H2C(Wr2.x), C2y = H2C(Wr2.y);
        float2 P5 = make_float2(0.f, 0.f);
        if (!CHK || (inc && (unsigned)(f0 - 2 + fr) < F_)) {
            __half2 dudx = __hmul2(e8h, __hfma2(twoh, __hsub2(B2x, B0x),
                             __hadd2(__hsub2(A2x, A0x), __hsub2(C2x, C0x))));
            __half2 dvdx = __hmul2(e8h, __hfma2(twoh, __hsub2(B2y, B0y),
                             __hadd2(__hsub2(A2y, A0y), __hsub2(C2y, C0y))));
            __half2 dudy = __hmul2(e8h, __hfma2(twoh, __hsub2(C1x, A1x),
                             __hadd2(__hsub2(C0x, A0x), __hsub2(C2x, A2x))));
            __half2 dvdy = __hmul2(e8h, __hfma2(twoh, __hsub2(C1y, A1y),
                             __hadd2(__hsub2(C0y, A0y), __hsub2(C2y, A2y))));
            __half2 c2 = __hfma2(dudx, dudx, __hfma2(dudy, dudy,
                         __hfma2(dvdx, dvdx, __hmul2(dvdy, dvdy))));
            float2 cf = __half22float2(c2);
            P5.x = sqrtf(cf.x + EPSV);
            P5.y = sqrtf(cf.y + EPSV);
        }
        *(unsigned*)(smb + FB_B + (fr * 36 + cc) * 4) = f2h(P5);
        A0x = B0x; A1x = B1x; A2x = B2x;
        A0y = B0y; A1y = B1y; A2y = B2y;
        B0x = C0x; B1x = C1x; B2x = C2x;
        B0y = C0y; B1y = C1y; B2y = C2y;
    }
}

__global__ void __launch_bounds__(256, 4)
asa_kernel(const float* __restrict__ spec, float* __restrict__ out)
{
    extern __shared__ float sm[];
    char*   smb = (char*)sm;
    float2* SX  = (float2*)smb;   // 40 x 41 channel pair (overlaid by HT later)

    const int tx  = threadIdx.x;   // 0..31
    const int ty  = threadIdx.y;   // 0..7
    const int tid = ty * 32 + tx;
    const int t0  = blockIdx.x * 32;
    const int f0  = blockIdx.y * 32;
    const int b   = blockIdx.z;

    const size_t FT   = (size_t)F_ * T_;
    const size_t MSTR = (size_t)B_ * FT;
    const float* img0 = spec + (size_t)(b * 2) * FT;
    const float* img1 = img0 + FT;
    float* obase = out + (size_t)b * FT + (size_t)(f0 + 4 * ty) * T_ + t0 + tx;

    const bool interior = (f0 >= 4) && (f0 + 36 <= F_) && (t0 >= 4) && (t0 + 36 <= T_);

    // ---- stage 0: load both channels into SX (float2), halo 4 ----
    if (interior) {
#pragma unroll
        for (int p = 0; p < 5; p++) {
            int r  = ty + 8 * p;
            const size_t o0 = (size_t)(f0 - 4 + r) * T_ + (t0 - 4);
            float2* row = SX + r * 41;
            row[tx] = make_float2(__ldg(img0 + o0 + tx), __ldg(img1 + o0 + tx));
            if (tx < 8)
                row[32 + tx] = make_float2(__ldg(img0 + o0 + 32 + tx),
                                           __ldg(img1 + o0 + 32 + tx));
        }
    } else {
#pragma unroll
        for (int p = 0; p < 5; p++) {
            int r  = ty + 8 * p;
            int gfr = f0 - 4 + r;
            float2* row = SX + r * 41;
            {
                int gt = t0 - 4 + tx;
                float2 v = make_float2(0.f, 0.f);
                if ((unsigned)gfr < F_ && (unsigned)gt < T_) {
                    size_t o = (size_t)gfr * T_ + gt;
                    v.x = __ldg(img0 + o);
                    v.y = __ldg(img1 + o);
                }
                row[tx] = v;
            }
            if (tx < 8) {
                int gt = t0 + 28 + tx;
                float2 v = make_float2(0.f, 0.f);
                if ((unsigned)gfr < F_ && (unsigned)gt < T_) {
                    size_t o = (size_t)gfr * T_ + gt;
                    v.x = __ldg(img0 + o);
                    v.y = __ldg(img1 + o);
                }
                row[32 + tx] = v;
            }
        }
    }
    __syncthreads();

    // ---- stage 0b: harmonic |2*v3 - v0 - v6| (channel pair) ----
    float2 harm[4];
    {
        float2 v[10];
#pragma unroll
        for (int j = 0; j < 10; j++)
            v[j] = SX[(4 * ty + 1 + j) * 41 + (tx + 4)];
#pragma unroll
        for (int k = 0; k < 4; k++) {
            harm[k].x = fabsf(2.f * v[k + 3].x - v[k].x - v[k + 6].x);
            harm[k].y = fabsf(2.f * v[k + 3].y - v[k].y - v[k + 6].y);
        }
    }

    // ---- stage 1: sobel + UU(fp16) + six F planes ----
    if (interior) stage1_run<false>(smb, SX, tid, t0, f0);
    else          stage1_run<true >(smb, SX, tid, t0, f0);
    __syncthreads();   // SX dead; HT overlays it from here

    const int rb = 4 * ty;
    // vertical 5-tap fully in half2; convert only the 4 results
#define VLOAD(pidx, s)                                                         \
    {                                                                          \
        const char* hb = smb + HT_B(pidx) + (tx * 36 + rb) * 4;                \
        uint4 qa = *(const uint4*)hb;                                          \
        uint4 qb = *(const uint4*)(hb + 16);                                   \
        __half2 r0 = g5h(H2C(qa.x), H2C(qa.y), H2C(qa.z), H2C(qa.w), H2C(qb.x)); \
        __half2 r1 = g5h(H2C(qa.y), H2C(qa.z), H2C(qa.w), H2C(qb.x), H2C(qb.y)); \
        __half2 r2 = g5h(H2C(qa.z), H2C(qa.w), H2C(qb.x), H2C(qb.y), H2C(qb.z)); \
        __half2 r3 = g5h(H2C(qa.w), H2C(qb.x), H2C(qb.y), H2C(qb.z), H2C(qb.w)); \
        s[0] = __half22float2(r0);                                             \
        s[1] = __half22float2(r1);                                             \
        s[2] = __half22float2(r2);                                             \
        s[3] = __half22float2(r3);                                             \
    }

    // ================= group 1: entropy (P0,P1,P2) =================
    {
        float2 sxx[4], syy[4], sxy[4];
        hpass_f(smb, FP_B(0), HT_B(0), tx, ty);
        hpass_f(smb, FP_B(1), HT_B(1), tx, ty);
        hpass_f(smb, FP_B(2), HT_B(2), tx, ty);
        __syncthreads();
        VLOAD(0, sxx) VLOAD(1, syy) VLOAD(2, sxy)
#pragma unroll
        for (int k = 0; k < 4; k++) {
            float e2 = 0.f;
#pragma unroll
            for (int ch = 0; ch < 2; ch++) {
                float vxx = ch ? sxx[k].y : sxx[k].x;
                float vyy = ch ? syy[k].y : syy[k].x;
                float vxy = ch ? sxy[k].y : sxy[k].x;
                float trace = vxx + vyy;
                float dif   = vxx - vyy;
                float disc  = sqrtf(fmaf(dif, dif, 4.f * vxy * vxy) + EPSV);
                float l1 = fmaxf((trace + disc) * 0.5f, EPSV);
                float l2 = fmaxf((trace - disc) * 0.5f, EPSV);
                float sinv = __fdividef(1.f, l1 + l2 + EPSV);
                float p1 = l1 * sinv, p2 = l2 * sinv;
                float ent = -(p1 * __logf(p1 + EPSV) + p2 * __logf(p2 + EPSV)) * 1.4426950408889634f;
                e2 += fminf(fmaxf(ent, 0.f), 1.f);
            }
            obase[k * T_] = e2 * 0.5f;
        }
    }
    __syncthreads();

    // ============ group 2: harmonic/temporal/spectral (P6,P7,P8) ============
    {
        float2 s6[4], s7[4], s8[4];
        hpass_f(smb, FP_B(3), HT_B(0), tx, ty);
        hpass_f(smb, FP_B(4), HT_B(1), tx, ty);
        hpass_f(smb, FP_B(5), HT_B(2), tx, ty);
        __syncthreads();
        VLOAD(0, s6) VLOAD(1, s7) VLOAD(2, s8)
#pragma unroll
        for (int k = 0; k < 4; k++) {
            float h0 = fminf(fmaxf(__fdividef(harm[k].x, s6[k].x + EPSV), 0.f), 1.f);
            float h1 = fminf(fmaxf(__fdividef(harm[k].y, s6[k].y + EPSV), 0.f), 1.f);
            obase[3 * MSTR + k * T_] = (h0 + h1) * 0.5f;
            float t0v = fminf(fmaxf(s7[k].x, 0.f), 1.f);
            float t1v = fminf(fmaxf(s7[k].y, 0.f), 1.f);
            obase[4 * MSTR + k * T_] = (t0v + t1v) * 0.5f;
            float sp0 = fminf(fmaxf(s8[k].x, 0.f), 1.f);
            float sp1 = fminf(fmaxf(s8[k].y, 0.f), 1.f);
            obase[5 * MSTR + k * T_] = (sp0 + sp1) * 0.5f;
        }
    }
    __syncthreads();

    // ============ group 3: alignment (UU) + curvature (FB overlays P0 slot) ============
    if (interior) curv_run<false>(smb, tid, t0, f0);
    else          curv_run<true >(smb, tid, t0, f0);
    {
        // horizontal pass for ux,uy directly from UU -> HT0, HT1 (independent of FB)
        int c0 = 4 * ty;
#pragma unroll
        for (int it = 0; it < 2; it++) {
            int r = (it == 0) ? tx : 32 + tx;
            if (it == 1 && tx >= 4) break;
            const char* ub = smb + UU_B + ((r + 1) * 39 + (c0 + 1)) * 8;
            uint2 u0 = *(const uint2*)(ub);
            uint2 u1 = *(const uint2*)(ub + 8);
            uint2 u2 = *(const uint2*)(ub + 16);
            uint2 u3 = *(const uint2*)(ub + 24);
            uint2 u4 = *(const uint2*)(ub + 32);
            uint2 u5 = *(const uint2*)(ub + 40);
            uint2 u6 = *(const uint2*)(ub + 48);
            uint2 u7 = *(const uint2*)(ub + 56);
#define HX(j) (*(__half2*)&u##j.x)
#define HY(j) (*(__half2*)&u##j.y)
            __half2 x0 = g5h(HX(0), HX(1), HX(2), HX(3), HX(4));
            __half2 x1 = g5h(HX(1), HX(2), HX(3), HX(4), HX(5));
            __half2 x2 = g5h(HX(2), HX(3), HX(4), HX(5), HX(6));
            __half2 x3 = g5h(HX(3), HX(4), HX(5), HX(6), HX(7));
            __half2 y0 = g5h(HY(0), HY(1), HY(2), HY(3), HY(4));
            __half2 y1 = g5h(HY(1), HY(2), HY(3), HY(4), HY(5));
            __half2 y2 = g5h(HY(2), HY(3), HY(4), HY(5), HY(6));
            __half2 y3 = g5h(HY(3), HY(4), HY(5), HY(6), HY(7));
#undef HX
#undef HY
            char* hb0 = smb + HT_B(0) + (c0 * 36 + r) * 4;
            *(unsigned*)(hb0)       = *(unsigned*)&x0;
            *(unsigned*)(hb0 + 144) = *(unsigned*)&x1;
            *(unsigned*)(hb0 + 288) = *(unsigned*)&x2;
            *(unsigned*)(hb0 + 432) = *(unsigned*)&x3;
            char* hb1 = smb + HT_B(1) + (c0 * 36 + r) * 4;
            *(unsigned*)(hb1)       = *(unsigned*)&y0;
            *(unsigned*)(hb1 + 144) = *(unsigned*)&y1;
            *(unsigned*)(hb1 + 288) = *(unsigned*)&y2;
            *(unsigned*)(hb1 + 432) = *(unsigned*)&y3;
        }
    }
    __syncthreads();                    // FB complete + HT0/1 complete
    hpass_f(smb, FB_B, HT_B(2), tx, ty);
    __syncthreads();
    {
        float2 sux[4], suy[4], scv[4];
        VLOAD(0, sux) VLOAD(1, suy) VLOAD(2, scv)
#pragma unroll
        for (int k = 0; k < 4; k++) {
            float a0 = fminf(sqrtf(fmaf(sux[k].x, sux[k].x, fmaf(suy[k].x, suy[k].x, EPSV))), 1.f);
            float a1 = fminf(sqrtf(fmaf(sux[k].y, sux[k].y, fmaf(suy[k].y, suy[k].y, EPSV))), 1.f);
            obase[MSTR + k * T_] = (a0 + a1) * 0.5f;
            obase[2 * MSTR + k * T_] = (scv[k].x + scv[k].y) * 0.5f;
        }
    }
#undef VLOAD
}

extern "C" void kernel_launch(void* const* d_in, const int* in_sizes, int n_in,
                              void* d_out, int out_size)
{
    const float* spec = (const float*)d_in[0];
    float* out = (float*)d_out;

    cudaFuncSetAttribute(asa_kernel, cudaFuncAttributeMaxDynamicSharedMemorySize, SMEM_BYTES);

    dim3 grid(T_ / 32, F_ / 32, B_);   // 4096 CTAs
    dim3 block(32, 8, 1);
    asa_kernel<<<grid, block, SMEM_BYTES>>>(spec, out);
}

// round 14
// speedup vs baseline: 1.6899x; 1.0597x over previous
#include <cuda_runtime.h>
#include <cuda_fp16.h>

#define B_ 8
#define C_ 2
#define F_ 256
#define T_ 2048
#define EPSV 1e-10f

// gaussian 1D (sigma=1, ws=5) separable factor, symmetric [W0,W1,W2,W1,W0]
#define W0 0.054488684548904895f
#define W1 0.24420134200323332f
#define W2 0.4026199468917436f

// ---- smem byte layout (channel-packed, 4 CTA/SM) ----
// HT scratch: 3 transposed planes [col 0..31][row 0..35] half2, col pitch 36 half2
//   HT_B(p) = p*4608 -> [0, 13824)
// SX float2 40x41 = 13120 overlays [0,13120) (dead after stage 1)
// UU @13824: 38x39 x uint2{half2 ux, half2 uy} = 11856 -> [13824, 25680)
// F planes @25680: 6 planes half2 36x36 pitch 36 (P0,P1,P2,P6,P7,P8), 5184 each -> 56784
// FB (curvature) overlays FP(0) after entropy group consumed it.
#define HT_B(p) ((p) * 4608)
#define UU_B    13824
#define FP_B(q) (25680 + (q) * 5184)
#define FB_B    FP_B(0)
#define SMEM_BYTES 56784

#define W0H __float2half2_rn(W0)
#define W1H __float2half2_rn(W1)
#define W2H __float2half2_rn(W2)

// ---- f32x2 packed helpers (sm_103a) ----
__device__ __forceinline__ float2 f2add(float2 a, float2 b) {
    unsigned long long ua = *(unsigned long long*)&a, ub = *(unsigned long long*)&b, ur;
    asm("add.rn.f32x2 %0, %1, %2;" : "=l"(ur) : "l"(ua), "l"(ub));
    return *(float2*)&ur;
}
__device__ __forceinline__ float2 f2mul(float2 a, float2 b) {
    unsigned long long ua = *(unsigned long long*)&a, ub = *(unsigned long long*)&b, ur;
    asm("mul.rn.f32x2 %0, %1, %2;" : "=l"(ur) : "l"(ua), "l"(ub));
    return *(float2*)&ur;
}
__device__ __forceinline__ float2 f2fma(float2 a, float2 b, float2 c) {
    unsigned long long ua = *(unsigned long long*)&a, ub = *(unsigned long long*)&b,
                       uc = *(unsigned long long*)&c, ur;
    asm("fma.rn.f32x2 %0, %1, %2, %3;" : "=l"(ur) : "l"(ua), "l"(ub), "l"(uc));
    return *(float2*)&ur;
}
__device__ __forceinline__ float2 f2sub(float2 a, float2 b) {
    return f2fma(b, make_float2(-1.f, -1.f), a);
}
// ---- single-MUFU approx transcendentals (args always >= 1e-30 here) ----
__device__ __forceinline__ float fsqrt_a(float x) {
    float r; asm("sqrt.approx.f32 %0, %1;" : "=f"(r) : "f"(x)); return r;
}
__device__ __forceinline__ float frsqrt_a(float x) {
    float r; asm("rsqrt.approx.f32 %0, %1;" : "=f"(r) : "f"(x)); return r;
}
__device__ __forceinline__ __half2 g5h(__half2 a, __half2 b, __half2 c, __half2 d, __half2 e) {
    return __hfma2(W0H, __hadd2(a, e), __hfma2(W1H, __hadd2(b, d), __hmul2(W2H, c)));
}
__device__ __forceinline__ float2 h2f(unsigned u) {
    __half2 h = *(__half2*)&u;
    return __half22float2(h);
}
__device__ __forceinline__ unsigned f2h(float2 v) {
    __half2 h = __floats2half2_rn(v.x, v.y);
    return *(unsigned*)&h;
}
#define H2C(u) (*(__half2*)&(u))

// single-plane horizontal 5-tap over an F plane (pitch 36 half2) -> transposed HT plane
// (per-plane dispatch: narrow live window — the flattened variant spilled, see R11)
__device__ __forceinline__ void hpass_f(char* smb, int fsrc_b, int htp_b, int tx, int ty) {
    int c0 = 4 * ty;
#pragma unroll
    for (int it = 0; it < 2; it++) {
        int r = (it == 0) ? tx : 32 + tx;
        if (it == 1 && tx >= 4) break;
        const char* fb = smb + fsrc_b + (r * 36 + c0) * 4;
        uint4 qa = *(const uint4*)fb;
        uint4 qb = *(const uint4*)(fb + 16);
        __half2 h0 = H2C(qa.x), h1 = H2C(qa.y), h2 = H2C(qa.z), h3 = H2C(qa.w);
        __half2 h4 = H2C(qb.x), h5 = H2C(qb.y), h6 = H2C(qb.z), h7 = H2C(qb.w);
        __half2 o0 = g5h(h0, h1, h2, h3, h4);
        __half2 o1 = g5h(h1, h2, h3, h4, h5);
        __half2 o2 = g5h(h2, h3, h4, h5, h6);
        __half2 o3 = g5h(h3, h4, h5, h6, h7);
        char* hb = smb + htp_b + (c0 * 36 + r) * 4;
        *(unsigned*)(hb)       = *(unsigned*)&o0;
        *(unsigned*)(hb + 144) = *(unsigned*)&o1;
        *(unsigned*)(hb + 288) = *(unsigned*)&o2;
        *(unsigned*)(hb + 432) = *(unsigned*)&o3;
    }
}

// ---- stage 1 specialized on border checking (CHK=false for interior CTAs) ----
template<bool CHK>
__device__ __forceinline__ void stage1_run(char* smb, const float2* SX,
                                           int tid, int t0, int f0)
{
    const float2 two = make_float2(2.f, 2.f);
    const float2 e8  = make_float2(0.125f, 0.125f);
    const float2 ep2 = make_float2(EPSV, EPSV);
    int cc = tid % 38;
    int q  = tid / 38;
    if (q < 6) {
        int r  = 7 * q;
        int rN = min(r + 7, 38);
        const float2* p = SX + r * 41 + cc;
        float2 a0 = p[0], a1 = p[1], a2 = p[2];
        p += 41;
        float2 b0 = p[0], b1 = p[1], b2 = p[2];
        bool inc = !CHK || (unsigned)(t0 - 3 + cc) < T_;
        for (; r < rN; r++) {
            const float2* pc = SX + (r + 2) * 41 + cc;
            float2 c0v = pc[0], c1v = pc[1], c2v = pc[2];
            float2 gtv = f2mul(e8, f2fma(two, f2sub(b2, b0),
                              f2add(f2sub(a2, a0), f2sub(c2v, c0v))));
            float2 gfv = f2mul(e8, f2fma(two, f2sub(c1v, a1),
                              f2add(f2sub(c0v, a0), f2sub(c2v, a2))));
            bool in = !CHK || (inc && ((unsigned)(f0 - 3 + r) < F_));
            float2 ux2 = make_float2(0.f, 0.f), uy2 = ux2;
            float2 txe = ux2;
            if (in) {
                txe = f2add(gtv, ep2);
                float2 r2v = f2fma(gfv, gfv, f2mul(txe, txe));
                float2 rin;
                rin.x = frsqrt_a(fmaxf(r2v.x, 1e-30f));
                rin.y = frsqrt_a(fmaxf(r2v.y, 1e-30f));
                ux2 = f2mul(txe, rin);
                uy2 = f2mul(gfv, rin);
            } else {
                gfv = make_float2(0.f, 0.f);
                gtv = gfv;
            }
            *(uint2*)(smb + UU_B + (r * 39 + cc) * 8) =
                make_uint2(f2h(ux2), f2h(uy2));
            if (r >= 1 && r <= 36 && cc >= 1 && cc <= 36) {
                int o = (r - 1) * 36 + (cc - 1);
                // mag2/r2 = 1 + O(eps/mag2): tensor fields collapse to raw products
                float2 P0 = f2mul(txe, txe);
                float2 P1 = f2mul(gfv, gfv);
                float2 P2 = f2mul(txe, gfv);
                float2 P6 = f2mul(b1, b1);       // b1 zero-filled at borders
                float2 P7, P8;
                if (in) {
                    P7.x = __fdividef(1.f, 1.f + fabsf(gtv.x));
                    P7.y = __fdividef(1.f, 1.f + fabsf(gtv.y));
                } else {
                    P7 = make_float2(0.f, 0.f);
                }
                P8.x = fabsf(gfv.x);
                P8.y = fabsf(gfv.y);
                *(unsigned*)(smb + FP_B(0) + o * 4) = f2h(P0);
                *(unsigned*)(smb + FP_B(1) + o * 4) = f2h(P1);
                *(unsigned*)(smb + FP_B(2) + o * 4) = f2h(P2);
                *(unsigned*)(smb + FP_B(3) + o * 4) = f2h(P6);
                *(unsigned*)(smb + FP_B(4) + o * 4) = f2h(P7);
                *(unsigned*)(smb + FP_B(5) + o * 4) = f2h(P8);
            }
            a0 = b0; a1 = b1; a2 = b2;
            b0 = c0v; b1 = c1v; b2 = c2v;
        }
    }
}

// ---- group-3 curvature: half2 window, fp32 approx sqrt, interior-templated ----
template<bool CHK>
__device__ __forceinline__ void curv_run(char* smb, int tid, int t0, int f0)
{
    int cc = tid % 36;
    int q  = tid / 36;
    if (q >= 6) return;
    const __half2 twoh = __float2half2_rn(2.f);
    const __half2 e8h  = __float2half2_rn(0.125f);
    int fr  = 6 * q;
    int frN = fr + 6;
    const uint2* up = (const uint2*)(smb + UU_B) + fr * 39 + cc;
    uint2 U0 = up[0], U1 = up[1], U2 = up[2];
    up += 39;
    uint2 V0 = up[0], V1 = up[1], V2 = up[2];
    __half2 A0x = H2C(U0.x), A0y = H2C(U0.y);
    __half2 A1x = H2C(U1.x), A1y = H2C(U1.y);
    __half2 A2x = H2C(U2.x), A2y = H2C(U2.y);
    __half2 B0x = H2C(V0.x), B0y = H2C(V0.y);
    __half2 B1x = H2C(V1.x), B1y = H2C(V1.y);
    __half2 B2x = H2C(V2.x), B2y = H2C(V2.y);
    bool inc = !CHK || (unsigned)(t0 - 2 + cc) < T_;
    for (; fr < frN; fr++) {
        const uint2* cp = (const uint2*)(smb + UU_B) + (fr + 2) * 39 + cc;
        uint2 Wr0 = cp[0], Wr1 = cp[1], Wr2 = cp[2];
        __half2 C0x = H2C(Wr0.x), C0y = H2C(Wr0.y);
        __half2 C1x = H2C(Wr1.x), C1y = H2C(Wr1.y);
        __half2 C2x = H2C(Wr2.x), C2y = H2C(Wr2.y);
        float2 P5 = make_float2(0.f, 0.f);
        if (!CHK || (inc && (unsigned)(f0 - 2 + fr) < F_)) {
            __half2 dudx = __hmul2(e8h, __hfma2(twoh, __hsub2(B2x, B0x),
                             __hadd2(__hsub2(A2x, A0x), __hsub2(C2x, C0x))));
            __half2 dvdx = __hmul2(e8h, __hfma2(twoh, __hsub2(B2y, B0y),
                             __hadd2(__hsub2(A2y, A0y), __hsub2(C2y, C0y))));
            __half2 dudy = __hmul2(e8h, __hfma2(twoh, __hsub2(C1x, A1x),
                             __hadd2(__hsub2(C0x, A0x), __hsub2(C2x, A2x))));
            __half2 dvdy = __hmul2(e8h, __hfma2(twoh, __hsub2(C1y, A1y),
                             __hadd2(__hsub2(C0y, A0y), __hsub2(C2y, A2y))));
            __half2 c2 = __hfma2(dudx, dudx, __hfma2(dudy, dudy,
                         __hfma2(dvdx, dvdx, __hmul2(dvdy, dvdy))));
            float2 cf = __half22float2(c2);
            P5.x = fsqrt_a(cf.x + EPSV);
            P5.y = fsqrt_a(cf.y + EPSV);
        }
        *(unsigned*)(smb + FB_B + (fr * 36 + cc) * 4) = f2h(P5);
        A0x = B0x; A1x = B1x; A2x = B2x;
        A0y = B0y; A1y = B1y; A2y = B2y;
        B0x = C0x; B1x = C1x; B2x = C2x;
        B0y = C0y; B1y = C1y; B2y = C2y;
    }
}

__global__ void __launch_bounds__(256, 4)
asa_kernel(const float* __restrict__ spec, float* __restrict__ out)
{
    extern __shared__ float sm[];
    char*   smb = (char*)sm;
    float2* SX  = (float2*)smb;   // 40 x 41 channel pair (overlaid by HT later)

    const int tx  = threadIdx.x;   // 0..31
    const int ty  = threadIdx.y;   // 0..7
    const int tid = ty * 32 + tx;
    const int t0  = blockIdx.x * 32;
    const int f0  = blockIdx.y * 32;
    const int b   = blockIdx.z;

    const size_t FT   = (size_t)F_ * T_;
    const size_t MSTR = (size_t)B_ * FT;
    const float* img0 = spec + (size_t)(b * 2) * FT;
    const float* img1 = img0 + FT;
    float* obase = out + (size_t)b * FT + (size_t)(f0 + 4 * ty) * T_ + t0 + tx;

    const bool interior = (f0 >= 4) && (f0 + 36 <= F_) && (t0 >= 4) && (t0 + 36 <= T_);

    // ---- stage 0: load both channels into SX (float2), halo 4 ----
    if (interior) {
#pragma unroll
        for (int p = 0; p < 5; p++) {
            int r  = ty + 8 * p;
            const size_t o0 = (size_t)(f0 - 4 + r) * T_ + (t0 - 4);
            float2* row = SX + r * 41;
            row[tx] = make_float2(__ldg(img0 + o0 + tx), __ldg(img1 + o0 + tx));
            if (tx < 8)
                row[32 + tx] = make_float2(__ldg(img0 + o0 + 32 + tx),
                                           __ldg(img1 + o0 + 32 + tx));
        }
    } else {
#pragma unroll
        for (int p = 0; p < 5; p++) {
            int r  = ty + 8 * p;
            int gfr = f0 - 4 + r;
            float2* row = SX + r * 41;
            {
                int gt = t0 - 4 + tx;
                float2 v = make_float2(0.f, 0.f);
                if ((unsigned)gfr < F_ && (unsigned)gt < T_) {
                    size_t o = (size_t)gfr * T_ + gt;
                    v.x = __ldg(img0 + o);
                    v.y = __ldg(img1 + o);
                }
                row[tx] = v;
            }
            if (tx < 8) {
                int gt = t0 + 28 + tx;
                float2 v = make_float2(0.f, 0.f);
                if ((unsigned)gfr < F_ && (unsigned)gt < T_) {
                    size_t o = (size_t)gfr * T_ + gt;
                    v.x = __ldg(img0 + o);
                    v.y = __ldg(img1 + o);
                }
                row[32 + tx] = v;
            }
        }
    }
    __syncthreads();

    // ---- stage 0b: harmonic |2*v3 - v0 - v6| (channel pair) ----
    float2 harm[4];
    {
        float2 v[10];
#pragma unroll
        for (int j = 0; j < 10; j++)
            v[j] = SX[(4 * ty + 1 + j) * 41 + (tx + 4)];
#pragma unroll
        for (int k = 0; k < 4; k++) {
            harm[k].x = fabsf(2.f * v[k + 3].x - v[k].x - v[k + 6].x);
            harm[k].y = fabsf(2.f * v[k + 3].y - v[k].y - v[k + 6].y);
        }
    }

    // ---- stage 1: sobel + UU(fp16) + six F planes ----
    if (interior) stage1_run<false>(smb, SX, tid, t0, f0);
    else          stage1_run<true >(smb, SX, tid, t0, f0);
    __syncthreads();   // SX dead; HT overlays it from here

    const int rb = 4 * ty;
    // vertical 5-tap fully in half2; convert only the 4 results
#define VLOAD(pidx, s)                                                         \
    {                                                                          \
        const char* hb = smb + HT_B(pidx) + (tx * 36 + rb) * 4;                \
        uint4 qa = *(const uint4*)hb;                                          \
        uint4 qb = *(const uint4*)(hb + 16);                                   \
        __half2 r0 = g5h(H2C(qa.x), H2C(qa.y), H2C(qa.z), H2C(qa.w), H2C(qb.x)); \
        __half2 r1 = g5h(H2C(qa.y), H2C(qa.z), H2C(qa.w), H2C(qb.x), H2C(qb.y)); \
        __half2 r2 = g5h(H2C(qa.z), H2C(qa.w), H2C(qb.x), H2C(qb.y), H2C(qb.z)); \
        __half2 r3 = g5h(H2C(qa.w), H2C(qb.x), H2C(qb.y), H2C(qb.z), H2C(qb.w)); \
        s[0] = __half22float2(r0);                                             \
        s[1] = __half22float2(r1);                                             \
        s[2] = __half22float2(r2);                                             \
        s[3] = __half22float2(r3);                                             \
    }

    // ================= group 1: entropy (P0,P1,P2) =================
    {
        float2 sxx[4], syy[4], sxy[4];
        hpass_f(smb, FP_B(0), HT_B(0), tx, ty);
        hpass_f(smb, FP_B(1), HT_B(1), tx, ty);
        hpass_f(smb, FP_B(2), HT_B(2), tx, ty);
        __syncthreads();
        VLOAD(0, sxx) VLOAD(1, syy) VLOAD(2, sxy)
#pragma unroll
        for (int k = 0; k < 4; k++) {
            float e2 = 0.f;
#pragma unroll
            for (int ch = 0; ch < 2; ch++) {
                float vxx = ch ? sxx[k].y : sxx[k].x;
                float vyy = ch ? syy[k].y : syy[k].x;
                float vxy = ch ? sxy[k].y : sxy[k].x;
                float trace = vxx + vyy;
                float dif   = vxx - vyy;
                float disc  = fsqrt_a(fmaf(dif, dif, 4.f * vxy * vxy) + EPSV);
                float l1 = fmaxf((trace + disc) * 0.5f, EPSV);
                float l2 = fmaxf((trace - disc) * 0.5f, EPSV);
                float sinv = __fdividef(1.f, l1 + l2 + EPSV);
                float p1 = l1 * sinv, p2 = l2 * sinv;
                float ent = -(p1 * __logf(p1 + EPSV) + p2 * __logf(p2 + EPSV)) * 1.4426950408889634f;
                e2 += fminf(fmaxf(ent, 0.f), 1.f);
            }
            obase[k * T_] = e2 * 0.5f;
        }
    }
    __syncthreads();

    // ============ group 2: harmonic/temporal/spectral (P6,P7,P8) ============
    {
        float2 s6[4], s7[4], s8[4];
        hpass_f(smb, FP_B(3), HT_B(0), tx, ty);
        hpass_f(smb, FP_B(4), HT_B(1), tx, ty);
        hpass_f(smb, FP_B(5), HT_B(2), tx, ty);
        __syncthreads();
        VLOAD(0, s6) VLOAD(1, s7) VLOAD(2, s8)
#pragma unroll
        for (int k = 0; k < 4; k++) {
            float h0 = fminf(fmaxf(__fdividef(harm[k].x, s6[k].x + EPSV), 0.f), 1.f);
            float h1 = fminf(fmaxf(__fdividef(harm[k].y, s6[k].y + EPSV), 0.f), 1.f);
            obase[3 * MSTR + k * T_] = (h0 + h1) * 0.5f;
            float t0v = fminf(fmaxf(s7[k].x, 0.f), 1.f);
            float t1v = fminf(fmaxf(s7[k].y, 0.f), 1.f);
            obase[4 * MSTR + k * T_] = (t0v + t1v) * 0.5f;
            float sp0 = fminf(fmaxf(s8[k].x, 0.f), 1.f);
            float sp1 = fminf(fmaxf(s8[k].y, 0.f), 1.f);
            obase[5 * MSTR + k * T_] = (sp0 + sp1) * 0.5f;
        }
    }
    __syncthreads();

    // ============ group 3: alignment (UU) + curvature (FB overlays P0 slot) ============
    if (interior) curv_run<false>(smb, tid, t0, f0);
    else          curv_run<true >(smb, tid, t0, f0);
    {
        // horizontal pass for ux,uy directly from UU -> HT0, HT1 (independent of FB)
        int c0 = 4 * ty;
#pragma unroll
        for (int it = 0; it < 2; it++) {
            int r = (it == 0) ? tx : 32 + tx;
            if (it == 1 && tx >= 4) break;
            const char* ub = smb + UU_B + ((r + 1) * 39 + (c0 + 1)) * 8;
            uint2 u0 = *(const uint2*)(ub);
            uint2 u1 = *(const uint2*)(ub + 8);
            uint2 u2 = *(const uint2*)(ub + 16);
            uint2 u3 = *(const uint2*)(ub + 24);
            uint2 u4 = *(const uint2*)(ub + 32);
            uint2 u5 = *(const uint2*)(ub + 40);
            uint2 u6 = *(const uint2*)(ub + 48);
            uint2 u7 = *(const uint2*)(ub + 56);
#define HX(j) (*(__half2*)&u##j.x)
#define HY(j) (*(__half2*)&u##j.y)
            __half2 x0 = g5h(HX(0), HX(1), HX(2), HX(3), HX(4));
            __half2 x1 = g5h(HX(1), HX(2), HX(3), HX(4), HX(5));
            __half2 x2 = g5h(HX(2), HX(3), HX(4), HX(5), HX(6));
            __half2 x3 = g5h(HX(3), HX(4), HX(5), HX(6), HX(7));
            __half2 y0 = g5h(HY(0), HY(1), HY(2), HY(3), HY(4));
            __half2 y1 = g5h(HY(1), HY(2), HY(3), HY(4), HY(5));
            __half2 y2 = g5h(HY(2), HY(3), HY(4), HY(5), HY(6));
            __half2 y3 = g5h(HY(3), HY(4), HY(5), HY(6), HY(7));
#undef HX
#undef HY
            char* hb0 = smb + HT_B(0) + (c0 * 36 + r) * 4;
            *(unsigned*)(hb0)       = *(unsigned*)&x0;
            *(unsigned*)(hb0 + 144) = *(unsigned*)&x1;
            *(unsigned*)(hb0 + 288) = *(unsigned*)&x2;
            *(unsigned*)(hb0 + 432) = *(unsigned*)&x3;
            char* hb1 = smb + HT_B(1) + (c0 * 36 + r) * 4;
            *(unsigned*)(hb1)       = *(unsigned*)&y0;
            *(unsigned*)(hb1 + 144) = *(unsigned*)&y1;
            *(unsigned*)(hb1 + 288) = *(unsigned*)&y2;
            *(unsigned*)(hb1 + 432) = *(unsigned*)&y3;
        }
    }
    __syncthreads();                    // FB complete + HT0/1 complete
    hpass_f(smb, FB_B, HT_B(2), tx, ty);
    __syncthreads();
    {
        float2 sux[4], suy[4], scv[4];
        VLOAD(0, sux) VLOAD(1, suy) VLOAD(2, scv)
#pragma unroll
        for (int k = 0; k < 4; k++) {
            float a0 = fminf(fsqrt_a(fmaf(sux[k].x, sux[k].x, fmaf(suy[k].x, suy[k].x, EPSV))), 1.f);
            float a1 = fminf(fsqrt_a(fmaf(sux[k].y, sux[k].y, fmaf(suy[k].y, suy[k].y, EPSV))), 1.f);
            obase[MSTR + k * T_] = (a0 + a1) * 0.5f;
            obase[2 * MSTR + k * T_] = (scv[k].x + scv[k].y) * 0.5f;
        }
    }
#undef VLOAD
}

extern "C" void kernel_launch(void* const* d_in, const int* in_sizes, int n_in,
                              void* d_out, int out_size)
{
    const float* spec = (const float*)d_in[0];
    float* out = (float*)d_out;

    cudaFuncSetAttribute(asa_kernel, cudaFuncAttributeMaxDynamicSharedMemorySize, SMEM_BYTES);

    dim3 grid(T_ / 32, F_ / 32, B_);   // 4096 CTAs
    dim3 block(32, 8, 1);
    asa_kernel<<<grid, block, SMEM_BYTES>>>(spec, out);
}

// round 15
// speedup vs baseline: 1.7022x; 1.0073x over previous
#include <cuda_runtime.h>
#include <cuda_fp16.h>

#define B_ 8
#define C_ 2
#define F_ 256
#define T_ 2048
#define EPSV 1e-10f

// gaussian 1D (sigma=1, ws=5) separable factor, symmetric [W0,W1,W2,W1,W0]
#define W0 0.054488684548904895f
#define W1 0.24420134200323332f
#define W2 0.4026199468917436f

// ---- smem byte layout (channel-packed, 4 CTA/SM) ----
// HT scratch: 3 transposed planes [col 0..31][row 0..35] half2, col pitch 36 half2
//   HT_B(p) = p*4608 -> [0, 13824)
// SX float2 40x41 = 13120 overlays [0,13120) (dead after stage 1)
// UU @13824: 38x39 x uint2{half2 ux, half2 uy} = 11856 -> [13824, 25680)
// F planes @25680: 6 planes half2 36x36 pitch 36 (P0,P1,P2,P6,P7,P8), 5184 each -> 56784
// FB (curvature) overlays FP(0) after entropy group consumed it.
#define HT_B(p) ((p) * 4608)
#define UU_B    13824
#define FP_B(q) (25680 + (q) * 5184)
#define FB_B    FP_B(0)
#define SMEM_BYTES 56784

#define W0H __float2half2_rn(W0)
#define W1H __float2half2_rn(W1)
#define W2H __float2half2_rn(W2)

// ---- f32x2 packed helpers (sm_103a) ----
__device__ __forceinline__ float2 f2add(float2 a, float2 b) {
    unsigned long long ua = *(unsigned long long*)&a, ub = *(unsigned long long*)&b, ur;
    asm("add.rn.f32x2 %0, %1, %2;" : "=l"(ur) : "l"(ua), "l"(ub));
    return *(float2*)&ur;
}
__device__ __forceinline__ float2 f2mul(float2 a, float2 b) {
    unsigned long long ua = *(unsigned long long*)&a, ub = *(unsigned long long*)&b, ur;
    asm("mul.rn.f32x2 %0, %1, %2;" : "=l"(ur) : "l"(ua), "l"(ub));
    return *(float2*)&ur;
}
__device__ __forceinline__ float2 f2fma(float2 a, float2 b, float2 c) {
    unsigned long long ua = *(unsigned long long*)&a, ub = *(unsigned long long*)&b,
                       uc = *(unsigned long long*)&c, ur;
    asm("fma.rn.f32x2 %0, %1, %2, %3;" : "=l"(ur) : "l"(ua), "l"(ub), "l"(uc));
    return *(float2*)&ur;
}
__device__ __forceinline__ float2 f2sub(float2 a, float2 b) {
    return f2fma(b, make_float2(-1.f, -1.f), a);
}
// ---- single-MUFU approx transcendentals (args always >= 1e-30 here) ----
__device__ __forceinline__ float fsqrt_a(float x) {
    float r; asm("sqrt.approx.f32 %0, %1;" : "=f"(r) : "f"(x)); return r;
}
__device__ __forceinline__ float frsqrt_a(float x) {
    float r; asm("rsqrt.approx.f32 %0, %1;" : "=f"(r) : "f"(x)); return r;
}
__device__ __forceinline__ float frcp_a(float x) {
    float r; asm("rcp.approx.f32 %0, %1;" : "=f"(r) : "f"(x)); return r;
}
__device__ __forceinline__ __half2 g5h(__half2 a, __half2 b, __half2 c, __half2 d, __half2 e) {
    return __hfma2(W0H, __hadd2(a, e), __hfma2(W1H, __hadd2(b, d), __hmul2(W2H, c)));
}
__device__ __forceinline__ float2 h2f(unsigned u) {
    __half2 h = *(__half2*)&u;
    return __half22float2(h);
}
__device__ __forceinline__ unsigned f2h(float2 v) {
    __half2 h = __floats2half2_rn(v.x, v.y);
    return *(unsigned*)&h;
}
#define H2C(u) (*(__half2*)&(u))

// single-plane horizontal 5-tap over an F plane (pitch 36 half2) -> transposed HT plane
// (per-plane dispatch: narrow live window — the flattened variant spilled, see R11)
__device__ __forceinline__ void hpass_f(char* smb, int fsrc_b, int htp_b, int tx, int ty) {
    int c0 = 4 * ty;
#pragma unroll
    for (int it = 0; it < 2; it++) {
        int r = (it == 0) ? tx : 32 + tx;
        if (it == 1 && tx >= 4) break;
        const char* fb = smb + fsrc_b + (r * 36 + c0) * 4;
        uint4 qa = *(const uint4*)fb;
        uint4 qb = *(const uint4*)(fb + 16);
        __half2 h0 = H2C(qa.x), h1 = H2C(qa.y), h2 = H2C(qa.z), h3 = H2C(qa.w);
        __half2 h4 = H2C(qb.x), h5 = H2C(qb.y), h6 = H2C(qb.z), h7 = H2C(qb.w);
        __half2 o0 = g5h(h0, h1, h2, h3, h4);
        __half2 o1 = g5h(h1, h2, h3, h4, h5);
        __half2 o2 = g5h(h2, h3, h4, h5, h6);
        __half2 o3 = g5h(h3, h4, h5, h6, h7);
        char* hb = smb + htp_b + (c0 * 36 + r) * 4;
        *(unsigned*)(hb)       = *(unsigned*)&o0;
        *(unsigned*)(hb + 144) = *(unsigned*)&o1;
        *(unsigned*)(hb + 288) = *(unsigned*)&o2;
        *(unsigned*)(hb + 432) = *(unsigned*)&o3;
    }
}

// ---- stage 1 specialized on border checking (CHK=false for interior CTAs) ----
template<bool CHK>
__device__ __forceinline__ void stage1_run(char* smb, const float2* SX,
                                           int tid, int t0, int f0)
{
    const float2 two = make_float2(2.f, 2.f);
    const float2 e8  = make_float2(0.125f, 0.125f);
    const float2 ep2 = make_float2(EPSV, EPSV);
    int cc = tid % 38;
    int q  = tid / 38;
    if (q < 6) {
        int r  = 7 * q;
        int rN = min(r + 7, 38);
        const float2* p = SX + r * 41 + cc;
        float2 a0 = p[0], a1 = p[1], a2 = p[2];
        p += 41;
        float2 b0 = p[0], b1 = p[1], b2 = p[2];
        bool inc = !CHK || (unsigned)(t0 - 3 + cc) < T_;
        for (; r < rN; r++) {
            const float2* pc = SX + (r + 2) * 41 + cc;
            float2 c0v = pc[0], c1v = pc[1], c2v = pc[2];
            float2 gtv = f2mul(e8, f2fma(two, f2sub(b2, b0),
                              f2add(f2sub(a2, a0), f2sub(c2v, c0v))));
            float2 gfv = f2mul(e8, f2fma(two, f2sub(c1v, a1),
                              f2add(f2sub(c0v, a0), f2sub(c2v, a2))));
            bool in = !CHK || (inc && ((unsigned)(f0 - 3 + r) < F_));
            float2 ux2 = make_float2(0.f, 0.f), uy2 = ux2;
            float2 txe = ux2;
            if (in) {
                txe = f2add(gtv, ep2);
                float2 r2v = f2fma(gfv, gfv, f2mul(txe, txe));
                float2 rin;
                rin.x = frsqrt_a(fmaxf(r2v.x, 1e-30f));
                rin.y = frsqrt_a(fmaxf(r2v.y, 1e-30f));
                ux2 = f2mul(txe, rin);
                uy2 = f2mul(gfv, rin);
            } else {
                gfv = make_float2(0.f, 0.f);
                gtv = gfv;
            }
            *(uint2*)(smb + UU_B + (r * 39 + cc) * 8) =
                make_uint2(f2h(ux2), f2h(uy2));
            if (r >= 1 && r <= 36 && cc >= 1 && cc <= 36) {
                int o = (r - 1) * 36 + (cc - 1);
                // mag2/r2 = 1 + O(eps/mag2): tensor fields collapse to raw products
                float2 P0 = f2mul(txe, txe);
                float2 P1 = f2mul(gfv, gfv);
                float2 P2 = f2mul(txe, gfv);
                float2 P6 = f2mul(b1, b1);       // b1 zero-filled at borders
                float2 P7, P8;
                if (in) {
                    P7.x = __fdividef(1.f, 1.f + fabsf(gtv.x));
                    P7.y = __fdividef(1.f, 1.f + fabsf(gtv.y));
                } else {
                    P7 = make_float2(0.f, 0.f);
                }
                P8.x = fabsf(gfv.x);
                P8.y = fabsf(gfv.y);
                *(unsigned*)(smb + FP_B(0) + o * 4) = f2h(P0);
                *(unsigned*)(smb + FP_B(1) + o * 4) = f2h(P1);
                *(unsigned*)(smb + FP_B(2) + o * 4) = f2h(P2);
                *(unsigned*)(smb + FP_B(3) + o * 4) = f2h(P6);
                *(unsigned*)(smb + FP_B(4) + o * 4) = f2h(P7);
                *(unsigned*)(smb + FP_B(5) + o * 4) = f2h(P8);
            }
            a0 = b0; a1 = b1; a2 = b2;
            b0 = c0v; b1 = c1v; b2 = c2v;
        }
    }
}

// ---- group-3 curvature: half2 window, fp32 approx sqrt, interior-templated ----
template<bool CHK>
__device__ __forceinline__ void curv_run(char* smb, int tid, int t0, int f0)
{
    int cc = tid % 36;
    int q  = tid / 36;
    if (q >= 6) return;
    const __half2 twoh = __float2half2_rn(2.f);
    const __half2 e8h  = __float2half2_rn(0.125f);
    int fr  = 6 * q;
    int frN = fr + 6;
    const uint2* up = (const uint2*)(smb + UU_B) + fr * 39 + cc;
    uint2 U0 = up[0], U1 = up[1], U2 = up[2];
    up += 39;
    uint2 V0 = up[0], V1 = up[1], V2 = up[2];
    __half2 A0x = H2C(U0.x), A0y = H2C(U0.y);
    __half2 A1x = H2C(U1.x), A1y = H2C(U1.y);
    __half2 A2x = H2C(U2.x), A2y = H2C(U2.y);
    __half2 B0x = H2C(V0.x), B0y = H2C(V0.y);
    __half2 B1x = H2C(V1.x), B1y = H2C(V1.y);
    __half2 B2x = H2C(V2.x), B2y = H2C(V2.y);
    bool inc = !CHK || (unsigned)(t0 - 2 + cc) < T_;
    for (; fr < frN; fr++) {
        const uint2* cp = (const uint2*)(smb + UU_B) + (fr + 2) * 39 + cc;
        uint2 Wr0 = cp[0], Wr1 = cp[1], Wr2 = cp[2];
        __half2 C0x = H2C(Wr0.x), C0y = H2C(Wr0.y);
        __half2 C1x = H2C(Wr1.x), C1y = H2C(Wr1.y);
        __half2 C2x = H2C(Wr2.x), C2y = H2C(Wr2.y);
        float2 P5 = make_float2(0.f, 0.f);
        if (!CHK || (inc && (unsigned)(f0 - 2 + fr) < F_)) {
            __half2 dudx = __hmul2(e8h, __hfma2(twoh, __hsub2(B2x, B0x),
                             __hadd2(__hsub2(A2x, A0x), __hsub2(C2x, C0x))));
            __half2 dvdx = __hmul2(e8h, __hfma2(twoh, __hsub2(B2y, B0y),
                             __hadd2(__hsub2(A2y, A0y), __hsub2(C2y, C0y))));
            __half2 dudy = __hmul2(e8h, __hfma2(twoh, __hsub2(C1x, A1x),
                             __hadd2(__hsub2(C0x, A0x), __hsub2(C2x, A2x))));
            __half2 dvdy = __hmul2(e8h, __hfma2(twoh, __hsub2(C1y, A1y),
                             __hadd2(__hsub2(C0y, A0y), __hsub2(C2y, A2y))));
            __half2 c2 = __hfma2(dudx, dudx, __hfma2(dudy, dudy,
                         __hfma2(dvdx, dvdx, __hmul2(dvdy, dvdy))));
            float2 cf = __half22float2(c2);
            P5.x = fsqrt_a(cf.x + EPSV);
            P5.y = fsqrt_a(cf.y + EPSV);
        }
        *(unsigned*)(smb + FB_B + (fr * 36 + cc) * 4) = f2h(P5);
        A0x = B0x; A1x = B1x; A2x = B2x;
        A0y = B0y; A1y = B1y; A2y = B2y;
        B0x = C0x; B1x = C1x; B2x = C2x;
        B0y = C0y; B1y = C1y; B2y = C2y;
    }
}

__global__ void __launch_bounds__(256, 4)
asa_kernel(const float* __restrict__ spec, float* __restrict__ out)
{
    extern __shared__ float sm[];
    char*   smb = (char*)sm;
    float2* SX  = (float2*)smb;   // 40 x 41 channel pair (overlaid by HT later)

    const int tx  = threadIdx.x;   // 0..31
    const int ty  = threadIdx.y;   // 0..7
    const int tid = ty * 32 + tx;
    const int t0  = blockIdx.x * 32;
    const int f0  = blockIdx.y * 32;
    const int b   = blockIdx.z;

    const size_t FT   = (size_t)F_ * T_;
    const size_t MSTR = (size_t)B_ * FT;
    const float* img0 = spec + (size_t)(b * 2) * FT;
    const float* img1 = img0 + FT;
    float* obase = out + (size_t)b * FT + (size_t)(f0 + 4 * ty) * T_ + t0 + tx;

    const bool interior = (f0 >= 4) && (f0 + 36 <= F_) && (t0 >= 4) && (t0 + 36 <= T_);

    // ---- stage 0: load both channels into SX (float2), halo 4 ----
    if (interior) {
#pragma unroll
        for (int p = 0; p < 5; p++) {
            int r  = ty + 8 * p;
            const size_t o0 = (size_t)(f0 - 4 + r) * T_ + (t0 - 4);
            float2* row = SX + r * 41;
            row[tx] = make_float2(__ldg(img0 + o0 + tx), __ldg(img1 + o0 + tx));
            if (tx < 8)
                row[32 + tx] = make_float2(__ldg(img0 + o0 + 32 + tx),
                                           __ldg(img1 + o0 + 32 + tx));
        }
    } else {
#pragma unroll
        for (int p = 0; p < 5; p++) {
            int r  = ty + 8 * p;
            int gfr = f0 - 4 + r;
            float2* row = SX + r * 41;
            {
                int gt = t0 - 4 + tx;
                float2 v = make_float2(0.f, 0.f);
                if ((unsigned)gfr < F_ && (unsigned)gt < T_) {
                    size_t o = (size_t)gfr * T_ + gt;
                    v.x = __ldg(img0 + o);
                    v.y = __ldg(img1 + o);
                }
                row[tx] = v;
            }
            if (tx < 8) {
                int gt = t0 + 28 + tx;
                float2 v = make_float2(0.f, 0.f);
                if ((unsigned)gfr < F_ && (unsigned)gt < T_) {
                    size_t o = (size_t)gfr * T_ + gt;
                    v.x = __ldg(img0 + o);
                    v.y = __ldg(img1 + o);
                }
                row[32 + tx] = v;
            }
        }
    }
    __syncthreads();

    // ---- stage 0b: harmonic |2*v3 - v0 - v6| (channel pair) ----
    float2 harm[4];
    {
        float2 v[10];
#pragma unroll
        for (int j = 0; j < 10; j++)
            v[j] = SX[(4 * ty + 1 + j) * 41 + (tx + 4)];
#pragma unroll
        for (int k = 0; k < 4; k++) {
            harm[k].x = fabsf(2.f * v[k + 3].x - v[k].x - v[k + 6].x);
            harm[k].y = fabsf(2.f * v[k + 3].y - v[k].y - v[k + 6].y);
        }
    }

    // ---- stage 1: sobel + UU(fp16) + six F planes ----
    if (interior) stage1_run<false>(smb, SX, tid, t0, f0);
    else          stage1_run<true >(smb, SX, tid, t0, f0);
    __syncthreads();   // SX dead; HT overlays it from here

    const int rb = 4 * ty;
    // vertical 5-tap fully in half2; convert only the 4 results
#define VLOAD(pidx, s)                                                         \
    {                                                                          \
        const char* hb = smb + HT_B(pidx) + (tx * 36 + rb) * 4;                \
        uint4 qa = *(const uint4*)hb;                                          \
        uint4 qb = *(const uint4*)(hb + 16);                                   \
        __half2 r0 = g5h(H2C(qa.x), H2C(qa.y), H2C(qa.z), H2C(qa.w), H2C(qb.x)); \
        __half2 r1 = g5h(H2C(qa.y), H2C(qa.z), H2C(qa.w), H2C(qb.x), H2C(qb.y)); \
        __half2 r2 = g5h(H2C(qa.z), H2C(qa.w), H2C(qb.x), H2C(qb.y), H2C(qb.z)); \
        __half2 r3 = g5h(H2C(qa.w), H2C(qb.x), H2C(qb.y), H2C(qb.z), H2C(qb.w)); \
        s[0] = __half22float2(r0);                                             \
        s[1] = __half22float2(r1);                                             \
        s[2] = __half22float2(r2);                                             \
        s[3] = __half22float2(r3);                                             \
    }

    // ================= group 1: entropy (P0,P1,P2), f32x2-packed epilogue =================
    {
        float2 sxx[4], syy[4], sxy[4];
        hpass_f(smb, FP_B(0), HT_B(0), tx, ty);
        hpass_f(smb, FP_B(1), HT_B(1), tx, ty);
        hpass_f(smb, FP_B(2), HT_B(2), tx, ty);
        __syncthreads();
        VLOAD(0, sxx) VLOAD(1, syy) VLOAD(2, sxy)
        const float2 four = make_float2(4.f, 4.f);
        const float2 half2c = make_float2(0.5f, 0.5f);
        const float2 ep2 = make_float2(EPSV, EPSV);
#pragma unroll
        for (int k = 0; k < 4; k++) {
            float2 trace = f2add(sxx[k], syy[k]);
            float2 dif   = f2sub(sxx[k], syy[k]);
            float2 vxy   = sxy[k];
            float2 d2 = f2fma(dif, dif, f2fma(f2mul(vxy, vxy), four, ep2));
            float2 disc;
            disc.x = fsqrt_a(d2.x);
            disc.y = fsqrt_a(d2.y);
            float2 l1 = f2mul(f2add(trace, disc), half2c);
            float2 l2 = f2mul(f2sub(trace, disc), half2c);
            l1.x = fmaxf(l1.x, EPSV); l1.y = fmaxf(l1.y, EPSV);
            l2.x = fmaxf(l2.x, EPSV); l2.y = fmaxf(l2.y, EPSV);
            float2 s = f2add(f2add(l1, l2), ep2);
            float2 sinv;
            sinv.x = frcp_a(s.x);
            sinv.y = frcp_a(s.y);
            float2 p1 = f2mul(l1, sinv);
            float2 p2 = f2mul(l2, sinv);
            float e0 = -fmaf(p1.x, __log2f(p1.x + EPSV), p2.x * __log2f(p2.x + EPSV));
            float e1 = -fmaf(p1.y, __log2f(p1.y + EPSV), p2.y * __log2f(p2.y + EPSV));
            e0 = fminf(fmaxf(e0, 0.f), 1.f);
            e1 = fminf(fmaxf(e1, 0.f), 1.f);
            obase[k * T_] = (e0 + e1) * 0.5f;
        }
    }
    __syncthreads();

    // ============ group 2: harmonic/temporal/spectral (P6,P7,P8) ============
    {
        float2 s6[4], s7[4], s8[4];
        hpass_f(smb, FP_B(3), HT_B(0), tx, ty);
        hpass_f(smb, FP_B(4), HT_B(1), tx, ty);
        hpass_f(smb, FP_B(5), HT_B(2), tx, ty);
        __syncthreads();
        VLOAD(0, s6) VLOAD(1, s7) VLOAD(2, s8)
#pragma unroll
        for (int k = 0; k < 4; k++) {
            float h0 = fminf(fmaxf(__fdividef(harm[k].x, s6[k].x + EPSV), 0.f), 1.f);
            float h1 = fminf(fmaxf(__fdividef(harm[k].y, s6[k].y + EPSV), 0.f), 1.f);
            obase[3 * MSTR + k * T_] = (h0 + h1) * 0.5f;
            float t0v = fminf(fmaxf(s7[k].x, 0.f), 1.f);
            float t1v = fminf(fmaxf(s7[k].y, 0.f), 1.f);
            obase[4 * MSTR + k * T_] = (t0v + t1v) * 0.5f;
            float sp0 = fminf(fmaxf(s8[k].x, 0.f), 1.f);
            float sp1 = fminf(fmaxf(s8[k].y, 0.f), 1.f);
            obase[5 * MSTR + k * T_] = (sp0 + sp1) * 0.5f;
        }
    }
    __syncthreads();

    // ============ group 3: alignment (UU) + curvature (FB overlays P0 slot) ============
    if (interior) curv_run<false>(smb, tid, t0, f0);
    else          curv_run<true >(smb, tid, t0, f0);
    {
        // horizontal pass for ux,uy directly from UU -> HT0, HT1 (independent of FB)
        int c0 = 4 * ty;
#pragma unroll
        for (int it = 0; it < 2; it++) {
            int r = (it == 0) ? tx : 32 + tx;
            if (it == 1 && tx >= 4) break;
            const char* ub = smb + UU_B + ((r + 1) * 39 + (c0 + 1)) * 8;
            uint2 u0 = *(const uint2*)(ub);
            uint2 u1 = *(const uint2*)(ub + 8);
            uint2 u2 = *(const uint2*)(ub + 16);
            uint2 u3 = *(const uint2*)(ub + 24);
            uint2 u4 = *(const uint2*)(ub + 32);
            uint2 u5 = *(const uint2*)(ub + 40);
            uint2 u6 = *(const uint2*)(ub + 48);
            uint2 u7 = *(const uint2*)(ub + 56);
#define HX(j) (*(__half2*)&u##j.x)
#define HY(j) (*(__half2*)&u##j.y)
            __half2 x0 = g5h(HX(0), HX(1), HX(2), HX(3), HX(4));
            __half2 x1 = g5h(HX(1), HX(2), HX(3), HX(4), HX(5));
            __half2 x2 = g5h(HX(2), HX(3), HX(4), HX(5), HX(6));
            __half2 x3 = g5h(HX(3), HX(4), HX(5), HX(6), HX(7));
            __half2 y0 = g5h(HY(0), HY(1), HY(2), HY(3), HY(4));
            __half2 y1 = g5h(HY(1), HY(2), HY(3), HY(4), HY(5));
            __half2 y2 = g5h(HY(2), HY(3), HY(4), HY(5), HY(6));
            __half2 y3 = g5h(HY(3), HY(4), HY(5), HY(6), HY(7));
#undef HX
#undef HY
            char* hb0 = smb + HT_B(0) + (c0 * 36 + r) * 4;
            *(unsigned*)(hb0)       = *(unsigned*)&x0;
            *(unsigned*)(hb0 + 144) = *(unsigned*)&x1;
            *(unsigned*)(hb0 + 288) = *(unsigned*)&x2;
            *(unsigned*)(hb0 + 432) = *(unsigned*)&x3;
            char* hb1 = smb + HT_B(1) + (c0 * 36 + r) * 4;
            *(unsigned*)(hb1)       = *(unsigned*)&y0;
            *(unsigned*)(hb1 + 144) = *(unsigned*)&y1;
            *(unsigned*)(hb1 + 288) = *(unsigned*)&y2;
            *(unsigned*)(hb1 + 432) = *(unsigned*)&y3;
        }
    }
    __syncthreads();                    // FB complete + HT0/1 complete
    hpass_f(smb, FB_B, HT_B(2), tx, ty);
    __syncthreads();
    {
        float2 sux[4], suy[4], scv[4];
        VLOAD(0, sux) VLOAD(1, suy) VLOAD(2, scv)
        const float2 ep2 = make_float2(EPSV, EPSV);
#pragma unroll
        for (int k = 0; k < 4; k++) {
            float2 a2v = f2fma(sux[k], sux[k], f2fma(suy[k], suy[k], ep2));
            float a0 = fminf(fsqrt_a(a2v.x), 1.f);
            float a1 = fminf(fsqrt_a(a2v.y), 1.f);
            obase[MSTR + k * T_] = (a0 + a1) * 0.5f;
            obase[2 * MSTR + k * T_] = (scv[k].x + scv[k].y) * 0.5f;
        }
    }
#undef VLOAD
}

extern "C" void kernel_launch(void* const* d_in, const int* in_sizes, int n_in,
                              void* d_out, int out_size)
{
    const float* spec = (const float*)d_in[0];
    float* out = (float*)d_out;

    cudaFuncSetAttribute(asa_kernel, cudaFuncAttributeMaxDynamicSharedMemorySize, SMEM_BYTES);

    dim3 grid(T_ / 32, F_ / 32, B_);   // 4096 CTAs
    dim3 block(32, 8, 1);
    asa_kernel<<<grid, block, SMEM_BYTES>>>(spec, out);
}

// round 16
// speedup vs baseline: 1.8511x; 1.0875x over previous
#include <cuda_runtime.h>
#include <cuda_fp16.h>

#define B_ 8
#define C_ 2
#define F_ 256
#define T_ 2048
#define EPSV 1e-10f

// gaussian 1D (sigma=1, ws=5) separable factor, symmetric [W0,W1,W2,W1,W0]
#define W0 0.054488684548904895f
#define W1 0.24420134200323332f
#define W2 0.4026199468917436f

// ---- smem byte layout (channel-packed, 4 CTA/SM) ----
// HT scratch: 3 transposed planes [col 0..31][row 0..35] half2, col pitch 36 half2
//   HT_B(p) = p*4608 -> [0, 13824)
// SX float2 40x41 = 13120 overlays [0,13120) (dead after stage 1)
// UU @13824: 38x39 x uint2{half2 ux, half2 uy} = 11856 -> [13824, 25680)
// F planes @25680: 6 planes half2 36x36 pitch 36 (P0,P1,P2,P6,P7,P8), 5184 each -> 56784
// FB (curvature) overlays FP(0) after entropy group consumed it.
#define HT_B(p) ((p) * 4608)
#define UU_B    13824
#define FP_B(q) (25680 + (q) * 5184)
#define FB_B    FP_B(0)
#define SMEM_BYTES 56784

#define W0H __float2half2_rn(W0)
#define W1H __float2half2_rn(W1)
#define W2H __float2half2_rn(W2)

// ---- f32x2 packed helpers (sm_103a) ----
__device__ __forceinline__ float2 f2add(float2 a, float2 b) {
    unsigned long long ua = *(unsigned long long*)&a, ub = *(unsigned long long*)&b, ur;
    asm("add.rn.f32x2 %0, %1, %2;" : "=l"(ur) : "l"(ua), "l"(ub));
    return *(float2*)&ur;
}
__device__ __forceinline__ float2 f2mul(float2 a, float2 b) {
    unsigned long long ua = *(unsigned long long*)&a, ub = *(unsigned long long*)&b, ur;
    asm("mul.rn.f32x2 %0, %1, %2;" : "=l"(ur) : "l"(ua), "l"(ub));
    return *(float2*)&ur;
}
__device__ __forceinline__ float2 f2fma(float2 a, float2 b, float2 c) {
    unsigned long long ua = *(unsigned long long*)&a, ub = *(unsigned long long*)&b,
                       uc = *(unsigned long long*)&c, ur;
    asm("fma.rn.f32x2 %0, %1, %2, %3;" : "=l"(ur) : "l"(ua), "l"(ub), "l"(uc));
    return *(float2*)&ur;
}
__device__ __forceinline__ float2 f2sub(float2 a, float2 b) {
    return f2fma(b, make_float2(-1.f, -1.f), a);
}
// ---- single-MUFU approx transcendentals (args always >= 1e-30 here) ----
__device__ __forceinline__ float fsqrt_a(float x) {
    float r; asm("sqrt.approx.f32 %0, %1;" : "=f"(r) : "f"(x)); return r;
}
__device__ __forceinline__ float frsqrt_a(float x) {
    float r; asm("rsqrt.approx.f32 %0, %1;" : "=f"(r) : "f"(x)); return r;
}
__device__ __forceinline__ float frcp_a(float x) {
    float r; asm("rcp.approx.f32 %0, %1;" : "=f"(r) : "f"(x)); return r;
}
__device__ __forceinline__ __half2 g5h(__half2 a, __half2 b, __half2 c, __half2 d, __half2 e) {
    return __hfma2(W0H, __hadd2(a, e), __hfma2(W1H, __hadd2(b, d), __hmul2(W2H, c)));
}
__device__ __forceinline__ float2 h2f(unsigned u) {
    __half2 h = *(__half2*)&u;
    return __half22float2(h);
}
__device__ __forceinline__ unsigned f2h(float2 v) {
    __half2 h = __floats2half2_rn(v.x, v.y);
    return *(unsigned*)&h;
}
#define H2C(u) (*(__half2*)&(u))

// one row-segment of horizontal 5-tap: F plane (pitch 36 half2) row r, cols c0..c0+3
__device__ __forceinline__ void hrow(char* smb, int fsrc_b, int htp_b, int r, int c0) {
    const char* fb = smb + fsrc_b + (r * 36 + c0) * 4;
    uint4 qa = *(const uint4*)fb;
    uint4 qb = *(const uint4*)(fb + 16);
    __half2 h0 = H2C(qa.x), h1 = H2C(qa.y), h2 = H2C(qa.z), h3 = H2C(qa.w);
    __half2 h4 = H2C(qb.x), h5 = H2C(qb.y), h6 = H2C(qb.z), h7 = H2C(qb.w);
    __half2 o0 = g5h(h0, h1, h2, h3, h4);
    __half2 o1 = g5h(h1, h2, h3, h4, h5);
    __half2 o2 = g5h(h2, h3, h4, h5, h6);
    __half2 o3 = g5h(h3, h4, h5, h6, h7);
    char* hb = smb + htp_b + (c0 * 36 + r) * 4;
    *(unsigned*)(hb)       = *(unsigned*)&o0;
    *(unsigned*)(hb + 144) = *(unsigned*)&o1;
    *(unsigned*)(hb + 288) = *(unsigned*)&o2;
    *(unsigned*)(hb + 432) = *(unsigned*)&o3;
}

// horizontal 5-tap over a full plane. Main batch: every thread does one row-segment.
// Tail (rows 32..35 x 8 col-groups = 32 items) is COMPACTED into warp `wsel`
// (full 32-lane efficiency) instead of 4/32 lanes of all 8 warps.
__device__ __forceinline__ void hpass_f(char* smb, int fsrc_b, int htp_b,
                                        int tx, int ty, int tid, int wsel) {
    hrow(smb, fsrc_b, htp_b, tx, 4 * ty);
    if ((tid >> 5) == wsel) {
        int l = tid & 31;
        hrow(smb, fsrc_b, htp_b, 32 + (l & 3), 4 * (l >> 2));
    }
}

// one row-segment of the UU horizontal pass -> HT0 (ux), HT1 (uy)
__device__ __forceinline__ void uurow(char* smb, int r, int c0) {
    const char* ub = smb + UU_B + ((r + 1) * 39 + (c0 + 1)) * 8;
    uint2 u0 = *(const uint2*)(ub);
    uint2 u1 = *(const uint2*)(ub + 8);
    uint2 u2 = *(const uint2*)(ub + 16);
    uint2 u3 = *(const uint2*)(ub + 24);
    uint2 u4 = *(const uint2*)(ub + 32);
    uint2 u5 = *(const uint2*)(ub + 40);
    uint2 u6 = *(const uint2*)(ub + 48);
    uint2 u7 = *(const uint2*)(ub + 56);
#define HX(j) (*(__half2*)&u##j.x)
#define HY(j) (*(__half2*)&u##j.y)
    __half2 x0 = g5h(HX(0), HX(1), HX(2), HX(3), HX(4));
    __half2 x1 = g5h(HX(1), HX(2), HX(3), HX(4), HX(5));
    __half2 x2 = g5h(HX(2), HX(3), HX(4), HX(5), HX(6));
    __half2 x3 = g5h(HX(3), HX(4), HX(5), HX(6), HX(7));
    __half2 y0 = g5h(HY(0), HY(1), HY(2), HY(3), HY(4));
    __half2 y1 = g5h(HY(1), HY(2), HY(3), HY(4), HY(5));
    __half2 y2 = g5h(HY(2), HY(3), HY(4), HY(5), HY(6));
    __half2 y3 = g5h(HY(3), HY(4), HY(5), HY(6), HY(7));
#undef HX
#undef HY
    char* hb0 = smb + HT_B(0) + (c0 * 36 + r) * 4;
    *(unsigned*)(hb0)       = *(unsigned*)&x0;
    *(unsigned*)(hb0 + 144) = *(unsigned*)&x1;
    *(unsigned*)(hb0 + 288) = *(unsigned*)&x2;
    *(unsigned*)(hb0 + 432) = *(unsigned*)&x3;
    char* hb1 = smb + HT_B(1) + (c0 * 36 + r) * 4;
    *(unsigned*)(hb1)       = *(unsigned*)&y0;
    *(unsigned*)(hb1 + 144) = *(unsigned*)&y1;
    *(unsigned*)(hb1 + 288) = *(unsigned*)&y2;
    *(unsigned*)(hb1 + 432) = *(unsigned*)&y3;
}

// ---- stage 1 specialized on border checking (CHK=false for interior CTAs) ----
template<bool CHK>
__device__ __forceinline__ void stage1_run(char* smb, const float2* SX,
                                           int tid, int t0, int f0)
{
    const float2 two = make_float2(2.f, 2.f);
    const float2 e8  = make_float2(0.125f, 0.125f);
    const float2 ep2 = make_float2(EPSV, EPSV);
    int cc = tid % 38;
    int q  = tid / 38;
    if (q < 6) {
        int r  = 7 * q;
        int rN = min(r + 7, 38);
        const float2* p = SX + r * 41 + cc;
        float2 a0 = p[0], a1 = p[1], a2 = p[2];
        p += 41;
        float2 b0 = p[0], b1 = p[1], b2 = p[2];
        bool inc = !CHK || (unsigned)(t0 - 3 + cc) < T_;
        for (; r < rN; r++) {
            const float2* pc = SX + (r + 2) * 41 + cc;
            float2 c0v = pc[0], c1v = pc[1], c2v = pc[2];
            float2 gtv = f2mul(e8, f2fma(two, f2sub(b2, b0),
                              f2add(f2sub(a2, a0), f2sub(c2v, c0v))));
            float2 gfv = f2mul(e8, f2fma(two, f2sub(c1v, a1),
                              f2add(f2sub(c0v, a0), f2sub(c2v, a2))));
            bool in = !CHK || (inc && ((unsigned)(f0 - 3 + r) < F_));
            float2 ux2 = make_float2(0.f, 0.f), uy2 = ux2;
            float2 txe = ux2;
            if (in) {
                txe = f2add(gtv, ep2);
                float2 r2v = f2fma(gfv, gfv, f2mul(txe, txe));
                float2 rin;
                rin.x = frsqrt_a(fmaxf(r2v.x, 1e-30f));
                rin.y = frsqrt_a(fmaxf(r2v.y, 1e-30f));
                ux2 = f2mul(txe, rin);
                uy2 = f2mul(gfv, rin);
            } else {
                gfv = make_float2(0.f, 0.f);
                gtv = gfv;
            }
            *(uint2*)(smb + UU_B + (r * 39 + cc) * 8) =
                make_uint2(f2h(ux2), f2h(uy2));
            if (r >= 1 && r <= 36 && cc >= 1 && cc <= 36) {
                int o = (r - 1) * 36 + (cc - 1);
                float2 P0 = f2mul(txe, txe);
                float2 P1 = f2mul(gfv, gfv);
                float2 P2 = f2mul(txe, gfv);
                float2 P6 = f2mul(b1, b1);       // b1 zero-filled at borders
                float2 P7, P8;
                if (in) {
                    P7.x = __fdividef(1.f, 1.f + fabsf(gtv.x));
                    P7.y = __fdividef(1.f, 1.f + fabsf(gtv.y));
                } else {
                    P7 = make_float2(0.f, 0.f);
                }
                P8.x = fabsf(gfv.x);
                P8.y = fabsf(gfv.y);
                *(unsigned*)(smb + FP_B(0) + o * 4) = f2h(P0);
                *(unsigned*)(smb + FP_B(1) + o * 4) = f2h(P1);
                *(unsigned*)(smb + FP_B(2) + o * 4) = f2h(P2);
                *(unsigned*)(smb + FP_B(3) + o * 4) = f2h(P6);
                *(unsigned*)(smb + FP_B(4) + o * 4) = f2h(P7);
                *(unsigned*)(smb + FP_B(5) + o * 4) = f2h(P8);
            }
            a0 = b0; a1 = b1; a2 = b2;
            b0 = c0v; b1 = c1v; b2 = c2v;
        }
    }
}

// ---- group-3 curvature: half2 window, fp32 approx sqrt, interior-templated ----
template<bool CHK>
__device__ __forceinline__ void curv_run(char* smb, int tid, int t0, int f0)
{
    int cc = tid % 36;
    int q  = tid / 36;
    if (q >= 6) return;
    const __half2 twoh = __float2half2_rn(2.f);
    const __half2 e8h  = __float2half2_rn(0.125f);
    int fr  = 6 * q;
    int frN = fr + 6;
    const uint2* up = (const uint2*)(smb + UU_B) + fr * 39 + cc;
    uint2 U0 = up[0], U1 = up[1], U2 = up[2];
    up += 39;
    uint2 V0 = up[0], V1 = up[1], V2 = up[2];
    __half2 A0x = H2C(U0.x), A0y = H2C(U0.y);
    __half2 A1x = H2C(U1.x), A1y = H2C(U1.y);
    __half2 A2x = H2C(U2.x), A2y = H2C(U2.y);
    __half2 B0x = H2C(V0.x), B0y = H2C(V0.y);
    __half2 B1x = H2C(V1.x), B1y = H2C(V1.y);
    __half2 B2x = H2C(V2.x), B2y = H2C(V2.y);
    bool inc = !CHK || (unsigned)(t0 - 2 + cc) < T_;
    for (; fr < frN; fr++) {
        const uint2* cp = (const uint2*)(smb + UU_B) + (fr + 2) * 39 + cc;
        uint2 Wr0 = cp[0], Wr1 = cp[1], Wr2 = cp[2];
        __half2 C0x = H2C(Wr0.x), C0y = H2C(Wr0.y);
        __half2 C1x = H2C(Wr1.x), C1y = H2C(Wr1.y);
        __half2 C2x = H2C(Wr2.x), C2y = H2C(Wr2.y);
        float2 P5 = make_float2(0.f, 0.f);
        if (!CHK || (inc && (unsigned)(f0 - 2 + fr) < F_)) {
            __half2 dudx = __hmul2(e8h, __hfma2(twoh, __hsub2(B2x, B0x),
                             __hadd2(__hsub2(A2x, A0x), __hsub2(C2x, C0x))));
            __half2 dvdx = __hmul2(e8h, __hfma2(twoh, __hsub2(B2y, B0y),
                             __hadd2(__hsub2(A2y, A0y), __hsub2(C2y, C0y))));
            __half2 dudy = __hmul2(e8h, __hfma2(twoh, __hsub2(C1x, A1x),
                             __hadd2(__hsub2(C0x, A0x), __hsub2(C2x, A2x))));
            __half2 dvdy = __hmul2(e8h, __hfma2(twoh, __hsub2(C1y, A1y),
                             __hadd2(__hsub2(C0y, A0y), __hsub2(C2y, A2y))));
            __half2 c2 = __hfma2(dudx, dudx, __hfma2(dudy, dudy,
                         __hfma2(dvdx, dvdx, __hmul2(dvdy, dvdy))));
            float2 cf = __half22float2(c2);
            P5.x = fsqrt_a(cf.x + EPSV);
            P5.y = fsqrt_a(cf.y + EPSV);
        }
        *(unsigned*)(smb + FB_B + (fr * 36 + cc) * 4) = f2h(P5);
        A0x = B0x; A1x = B1x; A2x = B2x;
        A0y = B0y; A1y = B1y; A2y = B2y;
        B0x = C0x; B1x = C1x; B2x = C2x;
        B0y = C0y; B1y = C1y; B2y = C2y;
    }
}

__global__ void __launch_bounds__(256, 4)
asa_kernel(const float* __restrict__ spec, float* __restrict__ out)
{
    extern __shared__ float sm[];
    char*   smb = (char*)sm;
    float2* SX  = (float2*)smb;   // 40 x 41 channel pair (overlaid by HT later)

    const int tx  = threadIdx.x;   // 0..31
    const int ty  = threadIdx.y;   // 0..7
    const int tid = ty * 32 + tx;
    const int t0  = blockIdx.x * 32;
    const int f0  = blockIdx.y * 32;
    const int b   = blockIdx.z;

    const size_t FT   = (size_t)F_ * T_;
    const size_t MSTR = (size_t)B_ * FT;
    const float* img0 = spec + (size_t)(b * 2) * FT;
    const float* img1 = img0 + FT;
    float* obase = out + (size_t)b * FT + (size_t)(f0 + 4 * ty) * T_ + t0 + tx;

    const bool interior = (f0 >= 4) && (f0 + 36 <= F_) && (t0 >= 4) && (t0 + 36 <= T_);

    // ---- stage 0: load both channels into SX (float2), halo 4 ----
    if (interior) {
#pragma unroll
        for (int p = 0; p < 5; p++) {
            int r  = ty + 8 * p;
            const size_t o0 = (size_t)(f0 - 4 + r) * T_ + (t0 - 4);
            float2* row = SX + r * 41;
            row[tx] = make_float2(__ldg(img0 + o0 + tx), __ldg(img1 + o0 + tx));
            if (tx < 8)
                row[32 + tx] = make_float2(__ldg(img0 + o0 + 32 + tx),
                                           __ldg(img1 + o0 + 32 + tx));
        }
    } else {
#pragma unroll
        for (int p = 0; p < 5; p++) {
            int r  = ty + 8 * p;
            int gfr = f0 - 4 + r;
            float2* row = SX + r * 41;
            {
                int gt = t0 - 4 + tx;
                float2 v = make_float2(0.f, 0.f);
                if ((unsigned)gfr < F_ && (unsigned)gt < T_) {
                    size_t o = (size_t)gfr * T_ + gt;
                    v.x = __ldg(img0 + o);
                    v.y = __ldg(img1 + o);
                }
                row[tx] = v;
            }
            if (tx < 8) {
                int gt = t0 + 28 + tx;
                float2 v = make_float2(0.f, 0.f);
                if ((unsigned)gfr < F_ && (unsigned)gt < T_) {
                    size_t o = (size_t)gfr * T_ + gt;
                    v.x = __ldg(img0 + o);
                    v.y = __ldg(img1 + o);
                }
                row[32 + tx] = v;
            }
        }
    }
    __syncthreads();

    // ---- stage 0b: harmonic |2*v3 - v0 - v6| (channel pair) ----
    float2 harm[4];
    {
        float2 v[10];
#pragma unroll
        for (int j = 0; j < 10; j++)
            v[j] = SX[(4 * ty + 1 + j) * 41 + (tx + 4)];
#pragma unroll
        for (int k = 0; k < 4; k++) {
            harm[k].x = fabsf(2.f * v[k + 3].x - v[k].x - v[k + 6].x);
            harm[k].y = fabsf(2.f * v[k + 3].y - v[k].y - v[k + 6].y);
        }
    }

    // ---- stage 1: sobel + UU(fp16) + six F planes ----
    if (interior) stage1_run<false>(smb, SX, tid, t0, f0);
    else          stage1_run<true >(smb, SX, tid, t0, f0);
    __syncthreads();   // SX dead; HT overlays it from here

    const int rb = 4 * ty;
    // vertical 5-tap fully in half2; convert only the 4 results
#define VLOAD(pidx, s)                                                         \
    {                                                                          \
        const char* hb = smb + HT_B(pidx) + (tx * 36 + rb) * 4;                \
        uint4 qa = *(const uint4*)hb;                                          \
        uint4 qb = *(const uint4*)(hb + 16);                                   \
        __half2 r0 = g5h(H2C(qa.x), H2C(qa.y), H2C(qa.z), H2C(qa.w), H2C(qb.x)); \
        __half2 r1 = g5h(H2C(qa.y), H2C(qa.z), H2C(qa.w), H2C(qb.x), H2C(qb.y)); \
        __half2 r2 = g5h(H2C(qa.z), H2C(qa.w), H2C(qb.x), H2C(qb.y), H2C(qb.z)); \
        __half2 r3 = g5h(H2C(qa.w), H2C(qb.x), H2C(qb.y), H2C(qb.z), H2C(qb.w)); \
        s[0] = __half22float2(r0);                                             \
        s[1] = __half22float2(r1);                                             \
        s[2] = __half22float2(r2);                                             \
        s[3] = __half22float2(r3);                                             \
    }

    // ================= group 1: entropy (P0,P1,P2), f32x2-packed epilogue =================
    {
        float2 sxx[4], syy[4], sxy[4];
        hpass_f(smb, FP_B(0), HT_B(0), tx, ty, tid, 0);
        hpass_f(smb, FP_B(1), HT_B(1), tx, ty, tid, 1);
        hpass_f(smb, FP_B(2), HT_B(2), tx, ty, tid, 2);
        __syncthreads();
        VLOAD(0, sxx) VLOAD(1, syy) VLOAD(2, sxy)
        const float2 four = make_float2(4.f, 4.f);
        const float2 half2c = make_float2(0.5f, 0.5f);
        const float2 ep2 = make_float2(EPSV, EPSV);
#pragma unroll
        for (int k = 0; k < 4; k++) {
            float2 trace = f2add(sxx[k], syy[k]);
            float2 dif   = f2sub(sxx[k], syy[k]);
            float2 vxy   = sxy[k];
            float2 d2 = f2fma(dif, dif, f2fma(f2mul(vxy, vxy), four, ep2));
            float2 disc;
            disc.x = fsqrt_a(d2.x);
            disc.y = fsqrt_a(d2.y);
            float2 l1 = f2mul(f2add(trace, disc), half2c);
            float2 l2 = f2mul(f2sub(trace, disc), half2c);
            l1.x = fmaxf(l1.x, EPSV); l1.y = fmaxf(l1.y, EPSV);
            l2.x = fmaxf(l2.x, EPSV); l2.y = fmaxf(l2.y, EPSV);
            float2 s = f2add(f2add(l1, l2), ep2);
            float2 sinv;
            sinv.x = frcp_a(s.x);
            sinv.y = frcp_a(s.y);
            float2 p1 = f2mul(l1, sinv);
            float2 p2 = f2mul(l2, sinv);
            float e0 = -fmaf(p1.x, __log2f(p1.x + EPSV), p2.x * __log2f(p2.x + EPSV));
            float e1 = -fmaf(p1.y, __log2f(p1.y + EPSV), p2.y * __log2f(p2.y + EPSV));
            e0 = fminf(fmaxf(e0, 0.f), 1.f);
            e1 = fminf(fmaxf(e1, 0.f), 1.f);
            obase[k * T_] = (e0 + e1) * 0.5f;
        }
    }
    __syncthreads();

    // ============ group 2: harmonic/temporal/spectral (P6,P7,P8) ============
    {
        float2 s6[4], s7[4], s8[4];
        hpass_f(smb, FP_B(3), HT_B(0), tx, ty, tid, 3);
        hpass_f(smb, FP_B(4), HT_B(1), tx, ty, tid, 4);
        hpass_f(smb, FP_B(5), HT_B(2), tx, ty, tid, 5);
        __syncthreads();
        VLOAD(0, s6) VLOAD(1, s7) VLOAD(2, s8)
#pragma unroll
        for (int k = 0; k < 4; k++) {
            float h0 = fminf(fmaxf(__fdividef(harm[k].x, s6[k].x + EPSV), 0.f), 1.f);
            float h1 = fminf(fmaxf(__fdividef(harm[k].y, s6[k].y + EPSV), 0.f), 1.f);
            obase[3 * MSTR + k * T_] = (h0 + h1) * 0.5f;
            float t0v = fminf(fmaxf(s7[k].x, 0.f), 1.f);
            float t1v = fminf(fmaxf(s7[k].y, 0.f), 1.f);
            obase[4 * MSTR + k * T_] = (t0v + t1v) * 0.5f;
            float sp0 = fminf(fmaxf(s8[k].x, 0.f), 1.f);
            float sp1 = fminf(fmaxf(s8[k].y, 0.f), 1.f);
            obase[5 * MSTR + k * T_] = (sp0 + sp1) * 0.5f;
        }
    }
    __syncthreads();

    // ============ group 3: alignment (UU) + curvature (FB overlays P0 slot) ============
    if (interior) curv_run<false>(smb, tid, t0, f0);
    else          curv_run<true >(smb, tid, t0, f0);
    {
        // horizontal pass for ux,uy directly from UU -> HT0, HT1 (tail to warp 6)
        uurow(smb, tx, 4 * ty);
        if ((tid >> 5) == 6) {
            int l = tid & 31;
            uurow(smb, 32 + (l & 3), 4 * (l >> 2));
        }
    }
    __syncthreads();                    // FB complete + HT0/1 complete
    hpass_f(smb, FB_B, HT_B(2), tx, ty, tid, 7);
    __syncthreads();
    {
        float2 sux[4], suy[4], scv[4];
        VLOAD(0, sux) VLOAD(1, suy) VLOAD(2, scv)
        const float2 ep2 = make_float2(EPSV, EPSV);
#pragma unroll
        for (int k = 0; k < 4; k++) {
            float2 a2v = f2fma(sux[k], sux[k], f2fma(suy[k], suy[k], ep2));
            float a0 = fminf(fsqrt_a(a2v.x), 1.f);
            float a1 = fminf(fsqrt_a(a2v.y), 1.f);
            obase[MSTR + k * T_] = (a0 + a1) * 0.5f;
            obase[2 * MSTR + k * T_] = (scv[k].x + scv[k].y) * 0.5f;
        }
    }
#undef VLOAD
}

extern "C" void kernel_launch(void* const* d_in, const int* in_sizes, int n_in,
                              void* d_out, int out_size)
{
    const float* spec = (const float*)d_in[0];
    float* out = (float*)d_out;

    cudaFuncSetAttribute(asa_kernel, cudaFuncAttributeMaxDynamicSharedMemorySize, SMEM_BYTES);

    dim3 grid(T_ / 32, F_ / 32, B_);   // 4096 CTAs
    dim3 block(32, 8, 1);
    asa_kernel<<<grid, block, SMEM_BYTES>>>(spec, out);
}